// round 2
// baseline (speedup 1.0000x reference)
#include <cuda_runtime.h>
#include <math.h>

// Problem constants
#define Bn 16384
#define Dn 1024
#define En 6
#define Hn 256
#define TM 64      // tokens per expert tile
#define KC 32      // k-chunk

// ---------------- device scratch (no allocations allowed) ----------------
__device__ double g_load_sums[En];
__device__ int    g_expert_count[En];
__device__ int    g_expert_tok[En * Bn];
__device__ float  g_expert_wt[En * Bn];

// ---------------- kernel 0: zero output + counters ----------------
__global__ void zero_kernel(float* __restrict__ out, int n) {
    int i = blockIdx.x * blockDim.x + threadIdx.x;
    if (i < n) out[i] = 0.0f;
    if (blockIdx.x == 0 && threadIdx.x < En) {
        g_load_sums[threadIdx.x] = 0.0;
        g_expert_count[threadIdx.x] = 0;
    }
}

// ---------------- kernel 1: router ----------------
// One warp per token: logits = x@Wr + br, softmax, smooth, top-2, list push.
// Load sums accumulated in double (aux scalar is catastrophically cancellation-
// sensitive: log(load*E + 1e-9) with load*E ~= 1).
__global__ void router_kernel(const float* __restrict__ x,
                              const float* __restrict__ Wr,
                              const float* __restrict__ br) {
    __shared__ double s_load[En];
    int warp = threadIdx.x >> 5;
    int lane = threadIdx.x & 31;
    if (threadIdx.x < En) s_load[threadIdx.x] = 0.0;
    __syncthreads();

    int t = blockIdx.x * 8 + warp;
    if (t < Bn) {
        float acc[En];
#pragma unroll
        for (int e = 0; e < En; e++) acc[e] = 0.0f;

        const float* xr = x + (size_t)t * Dn;
        for (int d = lane; d < Dn; d += 32) {
            float xv = xr[d];
#pragma unroll
            for (int e = 0; e < En; e++)
                acc[e] = fmaf(xv, __ldg(Wr + d * En + e), acc[e]);
        }
#pragma unroll
        for (int off = 16; off > 0; off >>= 1) {
#pragma unroll
            for (int e = 0; e < En; e++)
                acc[e] += __shfl_xor_sync(0xffffffffu, acc[e], off);
        }

        if (lane == 0) {
            float p[En];
            float m = -1e30f;
#pragma unroll
            for (int e = 0; e < En; e++) {
                p[e] = acc[e] + br[e];
                m = fmaxf(m, p[e]);
            }
            float s = 0.0f;
#pragma unroll
            for (int e = 0; e < En; e++) { p[e] = expf(p[e] - m); s += p[e]; }
            float inv = 1.0f / s;
#pragma unroll
            for (int e = 0; e < En; e++)
                p[e] = 0.9f * p[e] * inv + (0.1f / 6.0f);   // (1-EPS)*softmax + EPS/E

#pragma unroll
            for (int e = 0; e < En; e++)
                atomicAdd(&s_load[e], (double)p[e]);

            // top-2 (first index wins ties; order irrelevant for the weighted sum)
            int i0 = 0;
#pragma unroll
            for (int e = 1; e < En; e++) if (p[e] > p[i0]) i0 = e;
            int i1 = (i0 == 0) ? 1 : 0;
#pragma unroll
            for (int e = 0; e < En; e++) if (e != i0 && p[e] > p[i1]) i1 = e;

            int pos0 = atomicAdd(&g_expert_count[i0], 1);
            g_expert_tok[i0 * Bn + pos0] = t;
            g_expert_wt[i0 * Bn + pos0] = p[i0];
            int pos1 = atomicAdd(&g_expert_count[i1], 1);
            g_expert_tok[i1 * Bn + pos1] = t;
            g_expert_wt[i1 * Bn + pos1] = p[i1];
        }
    }
    __syncthreads();
    if (threadIdx.x < En)
        atomicAdd(&g_load_sums[threadIdx.x], s_load[threadIdx.x]);
}

// ---------------- kernel 2: aux scalar (double internally) ----------------
__global__ void aux_kernel(float* __restrict__ out_aux) {
    double aux = 0.0;
#pragma unroll
    for (int e = 0; e < En; e++) {
        double load = g_load_sums[e] / (double)Bn;
        aux += load * log(load * (double)En + 1e-9);
    }
    out_aux[0] = (float)(aux / log((double)En + 1e-9));
}

// ---------------- kernel 3: expert MLP tiles ----------------
// block = 256 threads, TM=64 tokens of one expert.
// GEMM1: H64x256 = gelu(X64x1024 @ W1[e] + b1[e]) ; GEMM2: out += w * (H @ W2[e] + b2[e])
extern __shared__ float smem[];

__global__ void __launch_bounds__(256) expert_kernel(
    const float* __restrict__ x,
    const float* __restrict__ W1,
    const float* __restrict__ b1,
    const float* __restrict__ W2,
    const float* __restrict__ b2,
    float* __restrict__ out)
{
    float* Xs = smem;                    // TM*KC        = 2048 f
    float* Ws = Xs + TM * KC;            // KC*Hn        = 8192 f
    float* Hs = Ws + KC * Hn;            // TM*Hn        = 16384 f
    __shared__ int   toks[TM];
    __shared__ float twt[TM];

    int e = blockIdx.y;
    int cnt = g_expert_count[e];
    int base = blockIdx.x * TM;
    if (base >= cnt) return;

    int tid = threadIdx.x;
    if (tid < TM) {
        int i = base + tid;
        if (i < cnt) {
            toks[tid] = g_expert_tok[e * Bn + i];
            twt[tid]  = g_expert_wt[e * Bn + i];
        } else {
            toks[tid] = 0;       // pad: valid address, weight 0 -> contributes nothing
            twt[tid]  = 0.0f;
        }
    }
    __syncthreads();

    int tg = tid >> 5;   // token group (warp id): 8 groups x 8 tokens
    int hg = tid & 31;   // column group: 32 groups x 8 cols

    float acc[8][8];
#pragma unroll
    for (int i = 0; i < 8; i++)
#pragma unroll
        for (int j = 0; j < 8; j++) acc[i][j] = 0.0f;

    const float* W1e = W1 + (size_t)e * Dn * Hn;

    // ---- GEMM1: X[64x1024] @ W1e[1024x256] ----
    for (int kc = 0; kc < Dn; kc += KC) {
#pragma unroll
        for (int p = 0; p < 2; p++) {          // Xs: 64x32 gathered rows
            int f = tid + p * 256;
            int r = f >> 3, c = (f & 7) * 4;
            *(float4*)(Xs + r * KC + c) =
                *(const float4*)(x + (size_t)toks[r] * Dn + kc + c);
        }
#pragma unroll
        for (int p = 0; p < 8; p++) {          // Ws: 32x256 of W1
            int f = tid + p * 256;
            int r = f >> 6, c = (f & 63) * 4;
            *(float4*)(Ws + r * Hn + c) =
                *(const float4*)(W1e + (size_t)(kc + r) * Hn + c);
        }
        __syncthreads();

#pragma unroll 4
        for (int k = 0; k < KC; k++) {
            float a[8];
#pragma unroll
            for (int i = 0; i < 8; i++) a[i] = Xs[(tg * 8 + i) * KC + k];  // warp broadcast
            float4 w0 = *(float4*)(Ws + k * Hn + hg * 8);
            float4 w1 = *(float4*)(Ws + k * Hn + hg * 8 + 4);
            float bb[8] = {w0.x, w0.y, w0.z, w0.w, w1.x, w1.y, w1.z, w1.w};
#pragma unroll
            for (int i = 0; i < 8; i++)
#pragma unroll
                for (int j = 0; j < 8; j++)
                    acc[i][j] = fmaf(a[i], bb[j], acc[i][j]);
        }
        __syncthreads();
    }

    // epilogue 1: bias + exact gelu -> Hs
    {
        const float* b1e = b1 + e * Hn;
        float bb[8];
#pragma unroll
        for (int j = 0; j < 8; j++) bb[j] = b1e[hg * 8 + j];
#pragma unroll
        for (int i = 0; i < 8; i++) {
            float v[8];
#pragma unroll
            for (int j = 0; j < 8; j++) {
                float t = acc[i][j] + bb[j];
                v[j] = 0.5f * t * (1.0f + erff(t * 0.70710678118654752f));
            }
            float* hrow = Hs + (tg * 8 + i) * Hn + hg * 8;
            *(float4*)(hrow)     = make_float4(v[0], v[1], v[2], v[3]);
            *(float4*)(hrow + 4) = make_float4(v[4], v[5], v[6], v[7]);
        }
    }
    __syncthreads();

    // ---- GEMM2: H[64x256] @ W2e[256x1024], in 4 d-chunks of 256 ----
    const float* W2e = W2 + (size_t)e * Hn * Dn;
    const float* b2e = b2 + (size_t)e * Dn;

    for (int dc = 0; dc < Dn; dc += 256) {
#pragma unroll
        for (int i = 0; i < 8; i++)
#pragma unroll
            for (int j = 0; j < 8; j++) acc[i][j] = 0.0f;

        for (int hc = 0; hc < Hn; hc += KC) {
#pragma unroll
            for (int p = 0; p < 8; p++) {      // Ws: 32x256 of W2
                int f = tid + p * 256;
                int r = f >> 6, c = (f & 63) * 4;
                *(float4*)(Ws + r * 256 + c) =
                    *(const float4*)(W2e + (size_t)(hc + r) * Dn + dc + c);
            }
            __syncthreads();

#pragma unroll 4
            for (int k = 0; k < KC; k++) {
                float a[8];
#pragma unroll
                for (int i = 0; i < 8; i++)
                    a[i] = Hs[(tg * 8 + i) * Hn + hc + k];   // warp broadcast
                float4 w0 = *(float4*)(Ws + k * 256 + hg * 8);
                float4 w1 = *(float4*)(Ws + k * 256 + hg * 8 + 4);
                float bb[8] = {w0.x, w0.y, w0.z, w0.w, w1.x, w1.y, w1.z, w1.w};
#pragma unroll
                for (int i = 0; i < 8; i++)
#pragma unroll
                    for (int j = 0; j < 8; j++)
                        acc[i][j] = fmaf(a[i], bb[j], acc[i][j]);
            }
            __syncthreads();
        }

        // epilogue 2: weighted scatter-accumulate (each token hit by exactly 2 experts)
        float bb2[8];
#pragma unroll
        for (int j = 0; j < 8; j++) bb2[j] = b2e[dc + hg * 8 + j];
#pragma unroll
        for (int i = 0; i < 8; i++) {
            int   tok = toks[tg * 8 + i];
            float w   = twt[tg * 8 + i];
            float* orow = out + (size_t)tok * Dn + dc + hg * 8;
#pragma unroll
            for (int j = 0; j < 8; j++)
                atomicAdd(orow + j, w * (acc[i][j] + bb2[j]));
        }
    }
}

// ---------------- launch ----------------
extern "C" void kernel_launch(void* const* d_in, const int* in_sizes, int n_in,
                              void* d_out, int out_size) {
    const float* x  = (const float*)d_in[0];
    const float* Wr = (const float*)d_in[1];
    const float* br = (const float*)d_in[2];
    const float* W1 = (const float*)d_in[3];
    const float* b1 = (const float*)d_in[4];
    const float* W2 = (const float*)d_in[5];
    const float* b2 = (const float*)d_in[6];
    float* out = (float*)d_out;

    int smem_bytes = (TM * KC + KC * Hn + TM * Hn) * (int)sizeof(float); // 106496
    cudaFuncSetAttribute(expert_kernel,
                         cudaFuncAttributeMaxDynamicSharedMemorySize, smem_bytes);

    zero_kernel<<<(Bn * Dn + 255) / 256, 256>>>(out, Bn * Dn);
    router_kernel<<<Bn / 8, 256>>>(x, Wr, br);
    if (out_size > Bn * Dn)
        aux_kernel<<<1, 1>>>(out + (size_t)Bn * Dn);
    expert_kernel<<<dim3(Bn / TM, En), 256, smem_bytes>>>(x, W1, b1, W2, b2, out);
}

// round 4
// speedup vs baseline: 3.1367x; 3.1367x over previous
#include <cuda_runtime.h>
#include <cuda_bf16.h>
#include <math.h>
#include <stdint.h>

// Problem constants
#define Bn 16384
#define Dn 1024
#define En 6
#define Hn 256
#define TMk 128
#define BD 16777216

// ---------------- device scratch ----------------
__device__ double g_load_sums[En];
__device__ int    g_expert_count[En];
__device__ int    g_expert_tok[En * Bn];   // token | (slot<<30)
__device__ float  g_expert_wt[En * Bn];
__device__ __nv_bfloat16 g_Xh[Bn * Dn];
__device__ __nv_bfloat16 g_Xl[Bn * Dn];
__device__ __nv_bfloat16 g_W1Th[En * Hn * Dn];   // [e][h][d] hi  (K-major, n=h)
__device__ __nv_bfloat16 g_W1Tl[En * Hn * Dn];
__device__ __nv_bfloat16 g_W2Th[En * Dn * Hn];   // [e][d][h] hi  (K-major, n=d)
__device__ __nv_bfloat16 g_W2Tl[En * Dn * Hn];
__device__ float g_buf[2 * Bn * Dn];             // per-slot weighted expert outputs

// ---------------- helpers ----------------
__device__ __forceinline__ uint32_t smem_u32(const void* p) {
    uint32_t a;
    asm("{ .reg .u64 t; cvta.to.shared.u64 t, %1; cvt.u32.u64 %0, t; }" : "=r"(a) : "l"(p));
    return a;
}
__device__ __forceinline__ uint32_t sw(uint32_t o) { return o ^ ((o >> 3) & 0x70); }
__device__ __forceinline__ uint32_t pk(__nv_bfloat16 a, __nv_bfloat16 b) {
    uint16_t lo = *(uint16_t*)&a, hi = *(uint16_t*)&b;
    return (uint32_t)lo | ((uint32_t)hi << 16);
}
__device__ __forceinline__ void ldsm4(uint32_t* r, uint32_t a) {
    asm volatile("ldmatrix.sync.aligned.m8n8.x4.shared.b16 {%0,%1,%2,%3}, [%4];"
                 : "=r"(r[0]), "=r"(r[1]), "=r"(r[2]), "=r"(r[3]) : "r"(a));
}
__device__ __forceinline__ void mma_bf(float* c, const uint32_t* a, uint32_t b0, uint32_t b1) {
    asm volatile(
        "mma.sync.aligned.m16n8k16.row.col.f32.bf16.bf16.f32 "
        "{%0,%1,%2,%3}, {%4,%5,%6,%7}, {%8,%9}, {%0,%1,%2,%3};"
        : "+f"(c[0]), "+f"(c[1]), "+f"(c[2]), "+f"(c[3])
        : "r"(a[0]), "r"(a[1]), "r"(a[2]), "r"(a[3]), "r"(b0), "r"(b1));
}
__device__ __forceinline__ void cpa(uint32_t dst, const void* src) {
    asm volatile("cp.async.cg.shared.global [%0], [%1], 16;" :: "r"(dst), "l"(src));
}
__device__ __forceinline__ void cp_commit() { asm volatile("cp.async.commit_group;"); }
__device__ __forceinline__ void cp_wait0()  { asm volatile("cp.async.wait_group 0;"); }
__device__ __forceinline__ void cp_wait1()  { asm volatile("cp.async.wait_group 1;"); }
__device__ __forceinline__ float gelu(float t) {
    return 0.5f * t * (1.0f + erff(t * 0.70710678118654752f));
}

// ---------------- kernel: zero counters ----------------
__global__ void zero_counters() {
    if (threadIdx.x < En) {
        g_load_sums[threadIdx.x] = 0.0;
        g_expert_count[threadIdx.x] = 0;
    }
}

// ---------------- kernel: split x -> bf16 hi/lo ----------------
__global__ void split_x(const float* __restrict__ x) {
    size_t i = ((size_t)blockIdx.x * 256 + threadIdx.x) * 4;
    float4 v = *(const float4*)(x + i);
    __nv_bfloat16 h0 = __float2bfloat16_rn(v.x), h1 = __float2bfloat16_rn(v.y);
    __nv_bfloat16 h2 = __float2bfloat16_rn(v.z), h3 = __float2bfloat16_rn(v.w);
    __nv_bfloat16 l0 = __float2bfloat16_rn(v.x - __bfloat162float(h0));
    __nv_bfloat16 l1 = __float2bfloat16_rn(v.y - __bfloat162float(h1));
    __nv_bfloat16 l2 = __float2bfloat16_rn(v.z - __bfloat162float(h2));
    __nv_bfloat16 l3 = __float2bfloat16_rn(v.w - __bfloat162float(h3));
    *(uint2*)((char*)g_Xh + i * 2) = make_uint2(pk(h0, h1), pk(h2, h3));
    *(uint2*)((char*)g_Xl + i * 2) = make_uint2(pk(l0, l1), pk(l2, l3));
}

// ---------------- kernel: weight split+transpose ----------------
__global__ void transpose_split_kernel(const float* __restrict__ src, int R, int C, int which) {
    __shared__ float tile[32][33];
    int e = blockIdx.z;
    int c0 = blockIdx.x * 32, r0 = blockIdx.y * 32;
    const float* s = src + (size_t)e * R * C;
    __nv_bfloat16* dh = (which == 0 ? g_W1Th : g_W2Th) + (size_t)e * R * C;
    __nv_bfloat16* dl = (which == 0 ? g_W1Tl : g_W2Tl) + (size_t)e * R * C;
#pragma unroll
    for (int i = 0; i < 32; i += 8)
        tile[threadIdx.y + i][threadIdx.x] = s[(size_t)(r0 + threadIdx.y + i) * C + c0 + threadIdx.x];
    __syncthreads();
#pragma unroll
    for (int i = 0; i < 32; i += 8) {
        float v = tile[threadIdx.x][threadIdx.y + i];
        __nv_bfloat16 h = __float2bfloat16_rn(v);
        __nv_bfloat16 l = __float2bfloat16_rn(v - __bfloat162float(h));
        size_t o = (size_t)(c0 + threadIdx.y + i) * R + r0 + threadIdx.x;
        dh[o] = h; dl[o] = l;
    }
}

// ---------------- kernel: router ----------------
__global__ void router_kernel(const float* __restrict__ x,
                              const float* __restrict__ Wr,
                              const float* __restrict__ br) {
    __shared__ double s_load[En];
    int warp = threadIdx.x >> 5;
    int lane = threadIdx.x & 31;
    if (threadIdx.x < En) s_load[threadIdx.x] = 0.0;
    __syncthreads();

    int t = blockIdx.x * 8 + warp;
    if (t < Bn) {
        float acc[En];
#pragma unroll
        for (int e = 0; e < En; e++) acc[e] = 0.0f;
        const float* xr = x + (size_t)t * Dn;
        for (int d = lane; d < Dn; d += 32) {
            float xv = xr[d];
#pragma unroll
            for (int e = 0; e < En; e++)
                acc[e] = fmaf(xv, __ldg(Wr + d * En + e), acc[e]);
        }
#pragma unroll
        for (int off = 16; off > 0; off >>= 1)
#pragma unroll
            for (int e = 0; e < En; e++)
                acc[e] += __shfl_xor_sync(0xffffffffu, acc[e], off);

        if (lane == 0) {
            float p[En];
            float m = -1e30f;
#pragma unroll
            for (int e = 0; e < En; e++) { p[e] = acc[e] + br[e]; m = fmaxf(m, p[e]); }
            float s = 0.0f;
#pragma unroll
            for (int e = 0; e < En; e++) { p[e] = expf(p[e] - m); s += p[e]; }
            float inv = 1.0f / s;
#pragma unroll
            for (int e = 0; e < En; e++)
                p[e] = 0.9f * p[e] * inv + (0.1f / 6.0f);
#pragma unroll
            for (int e = 0; e < En; e++)
                atomicAdd(&s_load[e], (double)p[e]);

            int i0 = 0;
#pragma unroll
            for (int e = 1; e < En; e++) if (p[e] > p[i0]) i0 = e;
            int i1 = (i0 == 0) ? 1 : 0;
#pragma unroll
            for (int e = 0; e < En; e++) if (e != i0 && p[e] > p[i1]) i1 = e;

            int pos0 = atomicAdd(&g_expert_count[i0], 1);
            g_expert_tok[i0 * Bn + pos0] = t;
            g_expert_wt[i0 * Bn + pos0] = p[i0];
            int pos1 = atomicAdd(&g_expert_count[i1], 1);
            g_expert_tok[i1 * Bn + pos1] = t | (1 << 30);
            g_expert_wt[i1 * Bn + pos1] = p[i1];
        }
    }
    __syncthreads();
    if (threadIdx.x < En)
        atomicAdd(&g_load_sums[threadIdx.x], s_load[threadIdx.x]);
}

// ---------------- kernel: aux scalar ----------------
__global__ void aux_kernel(float* __restrict__ out_aux) {
    double aux = 0.0;
#pragma unroll
    for (int e = 0; e < En; e++) {
        double load = g_load_sums[e] / (double)Bn;
        aux += load * log(load * (double)En + 1e-9);
    }
    out_aux[0] = (float)(aux / log((double)En + 1e-9));
}

// ---------------- kernel: expert MLP via mma.sync split-bf16 ----------------
// Arena (192KB, offsets from 128B-aligned base):
//  GEMM1 buf b at b*98304: Xh+0(16K) Xl+16384 Wh+32768(32K) Wl+65536(32K)
//  Between GEMMs: Hh = 4 panels of 16K at 0..65535; Hl at 65536..131071
//  GEMM2 W2 buf b at 131072 + b*32768: hi+0(16K) lo+16384(16K)
#define ARENA_BYTES (196608 + 128)
extern __shared__ char dsm[];

__global__ void __launch_bounds__(512, 1) expert_kernel(
    const float* __restrict__ b1g, const float* __restrict__ b2g)
{
    __shared__ int   toks[TMk];
    __shared__ int   tslot[TMk];
    __shared__ float twt[TMk];
    __shared__ float b1s[Hn];
    __shared__ float b2s[Dn];

    int e = blockIdx.y;
    int cnt = g_expert_count[e];
    int base = blockIdx.x * TMk;
    if (base >= cnt) return;

    int tid = threadIdx.x;
    int wid = tid >> 5, lane = tid & 31;

    uint32_t raw = smem_u32(dsm);
    uint32_t sb  = (raw + 127u) & ~127u;
    char* arena  = dsm + (sb - raw);

    if (tid < TMk) {
        int i = base + tid;
        if (i < cnt) {
            int v = g_expert_tok[e * Bn + i];
            toks[tid] = v & 0x3FFFFFFF; tslot[tid] = v >> 30;
            twt[tid] = g_expert_wt[e * Bn + i];
        } else { toks[tid] = 0; tslot[tid] = 0; twt[tid] = 0.0f; }
    }
    if (tid < Hn) b1s[tid] = b1g[e * Hn + tid];
    for (int f = tid; f < Dn; f += 512) b2s[f] = b2g[e * Dn + f];
    __syncthreads();

    // ---- fragment address constants ----
    int g  = lane >> 3, r = lane & 7;
    int arow = (g & 1) * 8 + r, akoff = (g >> 1) * 16;   // A: lanes 0-7 m0-7 k0 | 8-15 m8-15 k0 | 16-23 m0-7 k16 | 24-31 m8-15 k16
    int brow = (g >> 1) * 8 + r, bkoff = (g & 1) * 16;   // B: lanes 0-7 n0-7 k0 | 8-15 n0-7 k16 | 16-23 n8-15 k0 | 24-31 n8-15 k16
    int warpM = wid & 3, warpN = wid >> 2;

    uint32_t aoff[2];
    aoff[0] = (uint32_t)(warpM * 32 + arow) * 128 + akoff;
    aoff[1] = aoff[0] + 16 * 128;
    uint32_t boff1[4];
#pragma unroll
    for (int j2 = 0; j2 < 4; j2++)
        boff1[j2] = (uint32_t)(warpN * 64 + j2 * 16 + brow) * 128 + bkoff;

    // ---- staging tables ----
    const char* srcXh[2]; const char* srcXl[2]; uint32_t dstX[2];
#pragma unroll
    for (int p = 0; p < 2; p++) {
        int f = tid + p * 512, row = f >> 3, seg = f & 7;
        srcXh[p] = (const char*)(g_Xh + (size_t)toks[row] * Dn) + seg * 16;
        srcXl[p] = (const char*)(g_Xl + (size_t)toks[row] * Dn) + seg * 16;
        dstX[p]  = sw((uint32_t)row * 128 + seg * 16);
    }
    const __nv_bfloat16* W1h = g_W1Th + (size_t)e * Hn * Dn;
    const __nv_bfloat16* W1l = g_W1Tl + (size_t)e * Hn * Dn;
    const char* srcWh[4]; const char* srcWl[4]; uint32_t dstW[4];
#pragma unroll
    for (int p = 0; p < 4; p++) {
        int f = tid + p * 512, row = f >> 3, seg = f & 7;
        srcWh[p] = (const char*)(W1h + (size_t)row * Dn) + seg * 16;
        srcWl[p] = (const char*)(W1l + (size_t)row * Dn) + seg * 16;
        dstW[p]  = sw((uint32_t)row * 128 + seg * 16);
    }

    auto stage1 = [&](int ci, uint32_t bb) {
        uint32_t o = (uint32_t)ci * 128;
#pragma unroll
        for (int p = 0; p < 2; p++) {
            cpa(bb + dstX[p],          srcXh[p] + o);
            cpa(bb + 16384 + dstX[p],  srcXl[p] + o);
        }
#pragma unroll
        for (int p = 0; p < 4; p++) {
            cpa(bb + 32768 + dstW[p],  srcWh[p] + o);
            cpa(bb + 65536 + dstW[p],  srcWl[p] + o);
        }
    };

    // ================= GEMM1: C1[128x256] = X[128x1024] @ W1 (3-term) =================
    float acc[2][8][4];
#pragma unroll
    for (int i = 0; i < 2; i++)
#pragma unroll
        for (int j = 0; j < 8; j++)
#pragma unroll
            for (int q = 0; q < 4; q++) acc[i][j][q] = 0.0f;

    uint32_t buf0 = sb, buf1 = sb + 98304;
    stage1(0, buf0); cp_commit();

    for (int ci = 0; ci < 16; ci++) {
        uint32_t cb = (ci & 1) ? buf1 : buf0;
        if (ci < 15) { stage1(ci + 1, (ci & 1) ? buf0 : buf1); cp_commit(); cp_wait1(); }
        else cp_wait0();
        __syncthreads();

        uint32_t xh = cb, xl = cb + 16384, wh = cb + 32768, wl = cb + 65536;
#pragma unroll
        for (int ks = 0; ks < 4; ks++) {
            uint32_t Ah[2][4], Al[2][4];
#pragma unroll
            for (int i = 0; i < 2; i++) {
                ldsm4(Ah[i], xh + sw(aoff[i] + ks * 32));
                ldsm4(Al[i], xl + sw(aoff[i] + ks * 32));
            }
#pragma unroll
            for (int j2 = 0; j2 < 4; j2++) {
                uint32_t Bh[4], Bl[4];
                ldsm4(Bh, wh + sw(boff1[j2] + ks * 32));
                ldsm4(Bl, wl + sw(boff1[j2] + ks * 32));
#pragma unroll
                for (int i = 0; i < 2; i++) {
                    mma_bf(acc[i][2 * j2],     Ah[i], Bh[0], Bh[1]);
                    mma_bf(acc[i][2 * j2 + 1], Ah[i], Bh[2], Bh[3]);
                    mma_bf(acc[i][2 * j2],     Ah[i], Bl[0], Bl[1]);
                    mma_bf(acc[i][2 * j2 + 1], Ah[i], Bl[2], Bl[3]);
                    mma_bf(acc[i][2 * j2],     Al[i], Bh[0], Bh[1]);
                    mma_bf(acc[i][2 * j2 + 1], Al[i], Bh[2], Bh[3]);
                }
            }
        }
        __syncthreads();
    }

    // ---- epilogue 1: bias + GELU + bf16 split -> H panels in smem ----
    {
        int mb = warpM * 32, nb = warpN * 64;
#pragma unroll
        for (int i = 0; i < 2; i++)
#pragma unroll
            for (int j = 0; j < 8; j++) {
                int m0 = mb + i * 16 + (lane >> 2);
                int n0 = nb + j * 8 + (lane & 3) * 2;
                float bb0 = b1s[n0], bb1 = b1s[n0 + 1];
#pragma unroll
                for (int hr = 0; hr < 2; hr++) {
                    int m = m0 + hr * 8;
                    float v0 = gelu(acc[i][j][hr * 2]     + bb0);
                    float v1 = gelu(acc[i][j][hr * 2 + 1] + bb1);
                    __nv_bfloat16 h0 = __float2bfloat16_rn(v0);
                    __nv_bfloat16 h1 = __float2bfloat16_rn(v1);
                    __nv_bfloat16 l0 = __float2bfloat16_rn(v0 - __bfloat162float(h0));
                    __nv_bfloat16 l1 = __float2bfloat16_rn(v1 - __bfloat162float(h1));
                    uint32_t off = ((uint32_t)(n0 >> 6)) * 16384 + sw((uint32_t)m * 128 + (n0 & 63) * 2);
                    *(uint32_t*)(arena + off)          = pk(h0, h1);
                    *(uint32_t*)(arena + 65536 + off)  = pk(l0, l1);
                }
            }
    }
    __syncthreads();

    // ================= GEMM2: out[128x1024] = H[128x256] @ W2 (3-term) =================
    const __nv_bfloat16* W2h = g_W2Th + (size_t)e * Dn * Hn;
    const __nv_bfloat16* W2l = g_W2Tl + (size_t)e * Dn * Hn;

    uint32_t boff2[2];
#pragma unroll
    for (int j2 = 0; j2 < 2; j2++)
        boff2[j2] = (uint32_t)(warpN * 32 + j2 * 16 + brow) * 128 + bkoff;

    uint32_t srcO2[2], dst2[2];
#pragma unroll
    for (int p = 0; p < 2; p++) {
        int f = tid + p * 512, row = f >> 3, seg = f & 7;
        srcO2[p] = (uint32_t)row * 512 + seg * 16;
        dst2[p]  = sw((uint32_t)row * 128 + seg * 16);
    }
    auto stage2 = [&](int it, uint32_t bb) {
        int np = it >> 2, kc = it & 3;
        uint32_t o = (uint32_t)np * 65536 + (uint32_t)kc * 128;
#pragma unroll
        for (int p = 0; p < 2; p++) {
            cpa(bb + dst2[p],         (const char*)W2h + srcO2[p] + o);
            cpa(bb + 16384 + dst2[p], (const char*)W2l + srcO2[p] + o);
        }
    };

    uint32_t w2b0 = sb + 131072, w2b1 = sb + 163840;
    float acc2[2][4][4];
    stage2(0, w2b0); cp_commit();

    for (int it = 0; it < 32; it++) {
        int np = it >> 2, kc = it & 3;
        uint32_t cb = (it & 1) ? w2b1 : w2b0;
        if (it < 31) { stage2(it + 1, (it & 1) ? w2b0 : w2b1); cp_commit(); cp_wait1(); }
        else cp_wait0();
        __syncthreads();

        if (kc == 0) {
#pragma unroll
            for (int i = 0; i < 2; i++)
#pragma unroll
                for (int j = 0; j < 4; j++)
#pragma unroll
                    for (int q = 0; q < 4; q++) acc2[i][j][q] = 0.0f;
        }

        uint32_t ah = sb + kc * 16384, al = sb + 65536 + kc * 16384;
        uint32_t bh = cb, bl = cb + 16384;
#pragma unroll
        for (int ks = 0; ks < 4; ks++) {
            uint32_t Ah[2][4], Al[2][4];
#pragma unroll
            for (int i = 0; i < 2; i++) {
                ldsm4(Ah[i], ah + sw(aoff[i] + ks * 32));
                ldsm4(Al[i], al + sw(aoff[i] + ks * 32));
            }
#pragma unroll
            for (int j2 = 0; j2 < 2; j2++) {
                uint32_t Bh[4], Bl[4];
                ldsm4(Bh, bh + sw(boff2[j2] + ks * 32));
                ldsm4(Bl, bl + sw(boff2[j2] + ks * 32));
#pragma unroll
                for (int i = 0; i < 2; i++) {
                    mma_bf(acc2[i][2 * j2],     Ah[i], Bh[0], Bh[1]);
                    mma_bf(acc2[i][2 * j2 + 1], Ah[i], Bh[2], Bh[3]);
                    mma_bf(acc2[i][2 * j2],     Ah[i], Bl[0], Bl[1]);
                    mma_bf(acc2[i][2 * j2 + 1], Ah[i], Bl[2], Bl[3]);
                    mma_bf(acc2[i][2 * j2],     Al[i], Bh[0], Bh[1]);
                    mma_bf(acc2[i][2 * j2 + 1], Al[i], Bh[2], Bh[3]);
                }
            }
        }

        if (kc == 3) {
            // epilogue 2: weighted bias-add, direct per-slot store (no atomics)
            int mb = warpM * 32, nb = warpN * 32;
#pragma unroll
            for (int i = 0; i < 2; i++)
#pragma unroll
                for (int j = 0; j < 4; j++) {
                    int m0 = mb + i * 16 + (lane >> 2);
                    int n0 = np * 128 + nb + j * 8 + (lane & 3) * 2;
                    float bb0 = b2s[n0], bb1 = b2s[n0 + 1];
#pragma unroll
                    for (int hr = 0; hr < 2; hr++) {
                        int m = m0 + hr * 8;
                        if (base + m < cnt) {
                            int   tok  = toks[m];
                            int   slot = tslot[m];
                            float wgt  = twt[m];
                            float2 o;
                            o.x = wgt * (acc2[i][j][hr * 2]     + bb0);
                            o.y = wgt * (acc2[i][j][hr * 2 + 1] + bb1);
                            *(float2*)(g_buf + (size_t)slot * BD + (size_t)tok * Dn + n0) = o;
                        }
                    }
                }
        }
        __syncthreads();
    }
}

// ---------------- kernel: combine the two slots ----------------
__global__ void combine_kernel(float* __restrict__ out) {
    size_t i = ((size_t)blockIdx.x * 256 + threadIdx.x) * 4;
    float4 a = *(const float4*)(g_buf + i);
    float4 b = *(const float4*)(g_buf + (size_t)BD + i);
    *(float4*)(out + i) = make_float4(a.x + b.x, a.y + b.y, a.z + b.z, a.w + b.w);
}

// ---------------- launch ----------------
extern "C" void kernel_launch(void* const* d_in, const int* in_sizes, int n_in,
                              void* d_out, int out_size) {
    const float* x  = (const float*)d_in[0];
    const float* Wr = (const float*)d_in[1];
    const float* br = (const float*)d_in[2];
    const float* W1 = (const float*)d_in[3];
    const float* b1 = (const float*)d_in[4];
    const float* W2 = (const float*)d_in[5];
    const float* b2 = (const float*)d_in[6];
    float* out = (float*)d_out;

    cudaFuncSetAttribute(expert_kernel,
                         cudaFuncAttributeMaxDynamicSharedMemorySize, ARENA_BYTES);

    zero_counters<<<1, 32>>>();
    split_x<<<Bn * Dn / 1024, 256>>>(x);
    transpose_split_kernel<<<dim3(8, 32, En), dim3(32, 8)>>>(W1, Dn, Hn, 0);  // -> [e][h][d]
    transpose_split_kernel<<<dim3(32, 8, En), dim3(32, 8)>>>(W2, Hn, Dn, 1);  // -> [e][d][h]
    router_kernel<<<Bn / 8, 256>>>(x, Wr, br);
    if (out_size > BD)
        aux_kernel<<<1, 1>>>(out + (size_t)BD);
    expert_kernel<<<dim3(Bn / TMk, En), 512, ARENA_BYTES>>>(b1, b2);
    combine_kernel<<<BD / 1024, 256>>>(out);
}

// round 5
// speedup vs baseline: 3.5777x; 1.1406x over previous
#include <cuda_runtime.h>
#include <cuda_fp16.h>
#include <math.h>
#include <stdint.h>

// Problem constants
#define Bn 16384
#define Dn 1024
#define En 6
#define Hn 256
#define TMk 128
#define BD 16777216

// ---------------- device scratch ----------------
__device__ double g_load_sums[En];
__device__ int    g_expert_count[En];
__device__ int    g_expert_tok[En * Bn];   // token | (slot<<30)
__device__ float  g_expert_wt[En * Bn];
__device__ __half g_Xh[Bn * Dn];           // x hi (fp16)
__device__ __half g_Xl[Bn * Dn];           // x lo residual (fp16)
__device__ __half g_W1T[En * Hn * Dn];     // [e][h][d]  (K-major, n=h)
__device__ __half g_W2T[En * Dn * Hn];     // [e][d][h]  (K-major, n=d)
__device__ float  g_buf[2 * Bn * Dn];      // per-slot weighted expert outputs

// ---------------- helpers ----------------
__device__ __forceinline__ uint32_t smem_u32(const void* p) {
    uint32_t a;
    asm("{ .reg .u64 t; cvta.to.shared.u64 t, %1; cvt.u32.u64 %0, t; }" : "=r"(a) : "l"(p));
    return a;
}
__device__ __forceinline__ uint32_t sw(uint32_t o) { return o ^ ((o >> 3) & 0x70); }
__device__ __forceinline__ uint32_t pkh(__half a, __half b) {
    uint16_t lo = *(uint16_t*)&a, hi = *(uint16_t*)&b;
    return (uint32_t)lo | ((uint32_t)hi << 16);
}
__device__ __forceinline__ void ldsm4(uint32_t* r, uint32_t a) {
    asm volatile("ldmatrix.sync.aligned.m8n8.x4.shared.b16 {%0,%1,%2,%3}, [%4];"
                 : "=r"(r[0]), "=r"(r[1]), "=r"(r[2]), "=r"(r[3]) : "r"(a));
}
__device__ __forceinline__ void mma_h(float* c, const uint32_t* a, uint32_t b0, uint32_t b1) {
    asm volatile(
        "mma.sync.aligned.m16n8k16.row.col.f32.f16.f16.f32 "
        "{%0,%1,%2,%3}, {%4,%5,%6,%7}, {%8,%9}, {%0,%1,%2,%3};"
        : "+f"(c[0]), "+f"(c[1]), "+f"(c[2]), "+f"(c[3])
        : "r"(a[0]), "r"(a[1]), "r"(a[2]), "r"(a[3]), "r"(b0), "r"(b1));
}
__device__ __forceinline__ void cpa(uint32_t dst, const void* src) {
    asm volatile("cp.async.cg.shared.global [%0], [%1], 16;" :: "r"(dst), "l"(src));
}
__device__ __forceinline__ void cp_commit() { asm volatile("cp.async.commit_group;"); }
__device__ __forceinline__ void cp_wait0()  { asm volatile("cp.async.wait_group 0;"); }
__device__ __forceinline__ void cp_wait1()  { asm volatile("cp.async.wait_group 1;"); }
__device__ __forceinline__ float gelu(float t) {
    return 0.5f * t * (1.0f + erff(t * 0.70710678118654752f));
}

// ---------------- kernel: zero counters ----------------
__global__ void zero_counters() {
    if (threadIdx.x < En) {
        g_load_sums[threadIdx.x] = 0.0;
        g_expert_count[threadIdx.x] = 0;
    }
}

// ---------------- kernel: weight transpose -> fp16 ----------------
// src[e][R][C] fp32 -> dst[e][C][R] fp16
__global__ void transpose_half_kernel(const float* __restrict__ src, int R, int C, int which) {
    __shared__ float tile[32][33];
    int e = blockIdx.z;
    int c0 = blockIdx.x * 32, r0 = blockIdx.y * 32;
    const float* s = src + (size_t)e * R * C;
    __half* d = (which == 0 ? g_W1T : g_W2T) + (size_t)e * R * C;
#pragma unroll
    for (int i = 0; i < 32; i += 8)
        tile[threadIdx.y + i][threadIdx.x] = s[(size_t)(r0 + threadIdx.y + i) * C + c0 + threadIdx.x];
    __syncthreads();
#pragma unroll
    for (int i = 0; i < 32; i += 8) {
        size_t o = (size_t)(c0 + threadIdx.y + i) * R + r0 + threadIdx.x;
        d[o] = __float2half_rn(tile[threadIdx.x][threadIdx.y + i]);
    }
}

// ---------------- kernel: fused router + x split ----------------
// One warp per token: reads x row ONCE (float4), computes logits, softmax,
// top-2, list push, AND writes x hi/lo fp16.
__global__ void router_split_kernel(const float* __restrict__ x,
                                    const float* __restrict__ Wr,
                                    const float* __restrict__ br) {
    __shared__ double s_load[En];
    int warp = threadIdx.x >> 5;
    int lane = threadIdx.x & 31;
    if (threadIdx.x < En) s_load[threadIdx.x] = 0.0;
    __syncthreads();

    int t = blockIdx.x * 8 + warp;
    {
        float acc[En];
#pragma unroll
        for (int e = 0; e < En; e++) acc[e] = 0.0f;
        const float* xr = x + (size_t)t * Dn;
        char* dh = (char*)g_Xh + (size_t)t * Dn * 2;
        char* dl = (char*)g_Xl + (size_t)t * Dn * 2;
#pragma unroll
        for (int jj = 0; jj < 8; jj++) {
            int d0 = (lane + 32 * jj) * 4;
            float4 v = *(const float4*)(xr + d0);
            // logits
#pragma unroll
            for (int e = 0; e < En; e++) {
                acc[e] = fmaf(v.x, __ldg(Wr + (d0 + 0) * En + e), acc[e]);
                acc[e] = fmaf(v.y, __ldg(Wr + (d0 + 1) * En + e), acc[e]);
                acc[e] = fmaf(v.z, __ldg(Wr + (d0 + 2) * En + e), acc[e]);
                acc[e] = fmaf(v.w, __ldg(Wr + (d0 + 3) * En + e), acc[e]);
            }
            // split
            __half h0 = __float2half_rn(v.x), h1 = __float2half_rn(v.y);
            __half h2 = __float2half_rn(v.z), h3 = __float2half_rn(v.w);
            __half l0 = __float2half_rn(v.x - __half2float(h0));
            __half l1 = __float2half_rn(v.y - __half2float(h1));
            __half l2 = __float2half_rn(v.z - __half2float(h2));
            __half l3 = __float2half_rn(v.w - __half2float(h3));
            *(uint2*)(dh + d0 * 2) = make_uint2(pkh(h0, h1), pkh(h2, h3));
            *(uint2*)(dl + d0 * 2) = make_uint2(pkh(l0, l1), pkh(l2, l3));
        }
#pragma unroll
        for (int off = 16; off > 0; off >>= 1)
#pragma unroll
            for (int e = 0; e < En; e++)
                acc[e] += __shfl_xor_sync(0xffffffffu, acc[e], off);

        if (lane == 0) {
            float p[En];
            float m = -1e30f;
#pragma unroll
            for (int e = 0; e < En; e++) { p[e] = acc[e] + br[e]; m = fmaxf(m, p[e]); }
            float s = 0.0f;
#pragma unroll
            for (int e = 0; e < En; e++) { p[e] = expf(p[e] - m); s += p[e]; }
            float inv = 1.0f / s;
#pragma unroll
            for (int e = 0; e < En; e++)
                p[e] = 0.9f * p[e] * inv + (0.1f / 6.0f);
#pragma unroll
            for (int e = 0; e < En; e++)
                atomicAdd(&s_load[e], (double)p[e]);

            int i0 = 0;
#pragma unroll
            for (int e = 1; e < En; e++) if (p[e] > p[i0]) i0 = e;
            int i1 = (i0 == 0) ? 1 : 0;
#pragma unroll
            for (int e = 0; e < En; e++) if (e != i0 && p[e] > p[i1]) i1 = e;

            int pos0 = atomicAdd(&g_expert_count[i0], 1);
            g_expert_tok[i0 * Bn + pos0] = t;
            g_expert_wt[i0 * Bn + pos0] = p[i0];
            int pos1 = atomicAdd(&g_expert_count[i1], 1);
            g_expert_tok[i1 * Bn + pos1] = t | (1 << 30);
            g_expert_wt[i1 * Bn + pos1] = p[i1];
        }
    }
    __syncthreads();
    if (threadIdx.x < En)
        atomicAdd(&g_load_sums[threadIdx.x], s_load[threadIdx.x]);
}

// ---------------- kernel: aux scalar ----------------
__global__ void aux_kernel(float* __restrict__ out_aux) {
    double aux = 0.0;
#pragma unroll
    for (int e = 0; e < En; e++) {
        double load = g_load_sums[e] / (double)Bn;
        aux += load * log(load * (double)En + 1e-9);
    }
    out_aux[0] = (float)(aux / log((double)En + 1e-9));
}

// ---------------- kernel: expert MLP, fp16 2-term (exact-A-split, fp16 W) ----------------
// Arena (160KB, from 1KB-aligned base):
//  GEMM1 buf b at b*65536: Xh+0(16K) Xl+16384(16K) W+32768(32K)
//  Between GEMMs: Hh 4 panels of 16K at 0..65535; Hl at 65536..131071
//  GEMM2 W2 buf b at 131072 + b*16384 (16K each)
#define ARENA_BYTES (163840 + 1024)
extern __shared__ char dsm[];

__global__ void __launch_bounds__(512, 1) expert_kernel(
    const float* __restrict__ b1g, const float* __restrict__ b2g)
{
    __shared__ int   toks[TMk];
    __shared__ int   tslot[TMk];
    __shared__ float twt[TMk];
    __shared__ float b1s[Hn];
    __shared__ float b2s[Dn];

    int e = blockIdx.y;
    int cnt = g_expert_count[e];
    int base = blockIdx.x * TMk;
    if (base >= cnt) return;

    int tid = threadIdx.x;
    int wid = tid >> 5, lane = tid & 31;

    uint32_t raw = smem_u32(dsm);
    uint32_t sb  = (raw + 1023u) & ~1023u;
    char* arena  = dsm + (sb - raw);

    if (tid < TMk) {
        int i = base + tid;
        if (i < cnt) {
            int v = g_expert_tok[e * Bn + i];
            toks[tid] = v & 0x3FFFFFFF; tslot[tid] = v >> 30;
            twt[tid] = g_expert_wt[e * Bn + i];
        } else { toks[tid] = 0; tslot[tid] = 0; twt[tid] = 0.0f; }
    }
    if (tid < Hn) b1s[tid] = b1g[e * Hn + tid];
    for (int f = tid; f < Dn; f += 512) b2s[f] = b2g[e * Dn + f];
    __syncthreads();

    // ---- fragment address constants ----
    int g  = lane >> 3, r = lane & 7;
    int arow = (g & 1) * 8 + r, akoff = (g >> 1) * 16;
    int brow = (g >> 1) * 8 + r, bkoff = (g & 1) * 16;
    int warpM = wid & 3, warpN = wid >> 2;

    uint32_t aoff[2];
    aoff[0] = (uint32_t)(warpM * 32 + arow) * 128 + akoff;
    aoff[1] = aoff[0] + 16 * 128;
    uint32_t boff1[4];
#pragma unroll
    for (int j2 = 0; j2 < 4; j2++)
        boff1[j2] = (uint32_t)(warpN * 64 + j2 * 16 + brow) * 128 + bkoff;

    // ---- staging tables ----
    const char* srcXh[2]; const char* srcXl[2]; uint32_t dstX[2];
#pragma unroll
    for (int p = 0; p < 2; p++) {
        int f = tid + p * 512, row = f >> 3, seg = f & 7;
        srcXh[p] = (const char*)(g_Xh + (size_t)toks[row] * Dn) + seg * 16;
        srcXl[p] = (const char*)(g_Xl + (size_t)toks[row] * Dn) + seg * 16;
        dstX[p]  = sw((uint32_t)row * 128 + seg * 16);
    }
    const __half* W1t = g_W1T + (size_t)e * Hn * Dn;
    const char* srcW[4]; uint32_t dstW[4];
#pragma unroll
    for (int p = 0; p < 4; p++) {
        int f = tid + p * 512, row = f >> 3, seg = f & 7;
        srcW[p] = (const char*)(W1t + (size_t)row * Dn) + seg * 16;
        dstW[p] = sw((uint32_t)row * 128 + seg * 16);
    }

    auto stage1 = [&](int ci, uint32_t bb) {
        uint32_t o = (uint32_t)ci * 128;
#pragma unroll
        for (int p = 0; p < 2; p++) {
            cpa(bb + dstX[p],         srcXh[p] + o);
            cpa(bb + 16384 + dstX[p], srcXl[p] + o);
        }
#pragma unroll
        for (int p = 0; p < 4; p++)
            cpa(bb + 32768 + dstW[p], srcW[p] + o);
    };

    // ================= GEMM1: C1[128x256] = X[128x1024] @ W1 (2-term) =================
    float acc[2][8][4];
#pragma unroll
    for (int i = 0; i < 2; i++)
#pragma unroll
        for (int j = 0; j < 8; j++)
#pragma unroll
            for (int q = 0; q < 4; q++) acc[i][j][q] = 0.0f;

    uint32_t buf0 = sb, buf1 = sb + 65536;
    stage1(0, buf0); cp_commit();

    for (int ci = 0; ci < 16; ci++) {
        uint32_t cb = (ci & 1) ? buf1 : buf0;
        if (ci < 15) { stage1(ci + 1, (ci & 1) ? buf0 : buf1); cp_commit(); cp_wait1(); }
        else cp_wait0();
        __syncthreads();

        uint32_t xh = cb, xl = cb + 16384, wh = cb + 32768;
#pragma unroll
        for (int ks = 0; ks < 4; ks++) {
            uint32_t Ah[2][4], Al[2][4];
#pragma unroll
            for (int i = 0; i < 2; i++) {
                ldsm4(Ah[i], xh + sw(aoff[i] + ks * 32));
                ldsm4(Al[i], xl + sw(aoff[i] + ks * 32));
            }
#pragma unroll
            for (int j2 = 0; j2 < 4; j2++) {
                uint32_t Bh[4];
                ldsm4(Bh, wh + sw(boff1[j2] + ks * 32));
#pragma unroll
                for (int i = 0; i < 2; i++) {
                    mma_h(acc[i][2 * j2],     Ah[i], Bh[0], Bh[1]);
                    mma_h(acc[i][2 * j2 + 1], Ah[i], Bh[2], Bh[3]);
                    mma_h(acc[i][2 * j2],     Al[i], Bh[0], Bh[1]);
                    mma_h(acc[i][2 * j2 + 1], Al[i], Bh[2], Bh[3]);
                }
            }
        }
        __syncthreads();
    }

    // ---- prefetch first GEMM2 W2 stage (targets 131072+, no overlap with H) ----
    const __half* W2t = g_W2T + (size_t)e * Dn * Hn;
    uint32_t srcO2[2], dst2[2];
#pragma unroll
    for (int p = 0; p < 2; p++) {
        int f = tid + p * 512, row = f >> 3, seg = f & 7;
        srcO2[p] = (uint32_t)row * 512 + seg * 16;
        dst2[p]  = sw((uint32_t)row * 128 + seg * 16);
    }
    auto stage2 = [&](int it, uint32_t bb) {
        int np = it >> 2, kc = it & 3;
        uint32_t o = (uint32_t)np * 65536 + (uint32_t)kc * 128;
#pragma unroll
        for (int p = 0; p < 2; p++)
            cpa(bb + dst2[p], (const char*)W2t + srcO2[p] + o);
    };
    uint32_t w2b0 = sb + 131072, w2b1 = sb + 147456;
    stage2(0, w2b0); cp_commit();

    // ---- epilogue 1: bias + GELU + fp16 split -> H panels in smem ----
    {
        int mb = warpM * 32, nb = warpN * 64;
#pragma unroll
        for (int i = 0; i < 2; i++)
#pragma unroll
            for (int j = 0; j < 8; j++) {
                int m0 = mb + i * 16 + (lane >> 2);
                int n0 = nb + j * 8 + (lane & 3) * 2;
                float bb0 = b1s[n0], bb1 = b1s[n0 + 1];
#pragma unroll
                for (int hr = 0; hr < 2; hr++) {
                    int m = m0 + hr * 8;
                    float v0 = gelu(acc[i][j][hr * 2]     + bb0);
                    float v1 = gelu(acc[i][j][hr * 2 + 1] + bb1);
                    __half h0 = __float2half_rn(v0);
                    __half h1 = __float2half_rn(v1);
                    __half l0 = __float2half_rn(v0 - __half2float(h0));
                    __half l1 = __float2half_rn(v1 - __half2float(h1));
                    uint32_t off = ((uint32_t)(n0 >> 6)) * 16384 + sw((uint32_t)m * 128 + (n0 & 63) * 2);
                    *(uint32_t*)(arena + off)         = pkh(h0, h1);
                    *(uint32_t*)(arena + 65536 + off) = pkh(l0, l1);
                }
            }
    }
    __syncthreads();

    // ================= GEMM2: out[128x1024] = H[128x256] @ W2 (2-term) =================
    uint32_t boff2[2];
#pragma unroll
    for (int j2 = 0; j2 < 2; j2++)
        boff2[j2] = (uint32_t)(warpN * 32 + j2 * 16 + brow) * 128 + bkoff;

    float acc2[2][4][4];

    for (int it = 0; it < 32; it++) {
        int np = it >> 2, kc = it & 3;
        uint32_t cb = (it & 1) ? w2b1 : w2b0;
        if (it < 31) { stage2(it + 1, (it & 1) ? w2b0 : w2b1); cp_commit(); cp_wait1(); }
        else cp_wait0();
        __syncthreads();

        if (kc == 0) {
#pragma unroll
            for (int i = 0; i < 2; i++)
#pragma unroll
                for (int j = 0; j < 4; j++)
#pragma unroll
                    for (int q = 0; q < 4; q++) acc2[i][j][q] = 0.0f;
        }

        uint32_t ah = sb + kc * 16384, al = sb + 65536 + kc * 16384;
#pragma unroll
        for (int ks = 0; ks < 4; ks++) {
            uint32_t Ah[2][4], Al[2][4];
#pragma unroll
            for (int i = 0; i < 2; i++) {
                ldsm4(Ah[i], ah + sw(aoff[i] + ks * 32));
                ldsm4(Al[i], al + sw(aoff[i] + ks * 32));
            }
#pragma unroll
            for (int j2 = 0; j2 < 2; j2++) {
                uint32_t Bh[4];
                ldsm4(Bh, cb + sw(boff2[j2] + ks * 32));
#pragma unroll
                for (int i = 0; i < 2; i++) {
                    mma_h(acc2[i][2 * j2],     Ah[i], Bh[0], Bh[1]);
                    mma_h(acc2[i][2 * j2 + 1], Ah[i], Bh[2], Bh[3]);
                    mma_h(acc2[i][2 * j2],     Al[i], Bh[0], Bh[1]);
                    mma_h(acc2[i][2 * j2 + 1], Al[i], Bh[2], Bh[3]);
                }
            }
        }

        if (kc == 3) {
            // epilogue 2: weighted bias-add, direct per-slot store (no atomics)
            int mb = warpM * 32, nb = warpN * 32;
#pragma unroll
            for (int i = 0; i < 2; i++)
#pragma unroll
                for (int j = 0; j < 4; j++) {
                    int m0 = mb + i * 16 + (lane >> 2);
                    int n0 = np * 128 + nb + j * 8 + (lane & 3) * 2;
                    float bb0 = b2s[n0], bb1 = b2s[n0 + 1];
#pragma unroll
                    for (int hr = 0; hr < 2; hr++) {
                        int m = m0 + hr * 8;
                        if (base + m < cnt) {
                            int   tok  = toks[m];
                            int   slot = tslot[m];
                            float wgt  = twt[m];
                            float2 o;
                            o.x = wgt * (acc2[i][j][hr * 2]     + bb0);
                            o.y = wgt * (acc2[i][j][hr * 2 + 1] + bb1);
                            *(float2*)(g_buf + (size_t)slot * BD + (size_t)tok * Dn + n0) = o;
                        }
                    }
                }
        }
        __syncthreads();
    }
}

// ---------------- kernel: combine the two slots ----------------
__global__ void combine_kernel(float* __restrict__ out) {
    size_t i = ((size_t)blockIdx.x * 512 + threadIdx.x) * 4;
    float4 a = *(const float4*)(g_buf + i);
    float4 b = *(const float4*)(g_buf + (size_t)BD + i);
    *(float4*)(out + i) = make_float4(a.x + b.x, a.y + b.y, a.z + b.z, a.w + b.w);
}

// ---------------- launch ----------------
extern "C" void kernel_launch(void* const* d_in, const int* in_sizes, int n_in,
                              void* d_out, int out_size) {
    const float* x  = (const float*)d_in[0];
    const float* Wr = (const float*)d_in[1];
    const float* br = (const float*)d_in[2];
    const float* W1 = (const float*)d_in[3];
    const float* b1 = (const float*)d_in[4];
    const float* W2 = (const float*)d_in[5];
    const float* b2 = (const float*)d_in[6];
    float* out = (float*)d_out;

    cudaFuncSetAttribute(expert_kernel,
                         cudaFuncAttributeMaxDynamicSharedMemorySize, ARENA_BYTES);

    zero_counters<<<1, 32>>>();
    transpose_half_kernel<<<dim3(8, 32, En), dim3(32, 8)>>>(W1, Dn, Hn, 0);  // -> [e][h][d]
    transpose_half_kernel<<<dim3(32, 8, En), dim3(32, 8)>>>(W2, Hn, Dn, 1);  // -> [e][d][h]
    router_split_kernel<<<Bn / 8, 256>>>(x, Wr, br);
    if (out_size > BD)
        aux_kernel<<<1, 1>>>(out + (size_t)BD);
    expert_kernel<<<dim3(Bn / TMk, En), 512, ARENA_BYTES>>>(b1, b2);
    combine_kernel<<<BD / 2048, 512>>>(out);
}

// round 6
// speedup vs baseline: 4.1496x; 1.1598x over previous
#include <cuda_runtime.h>
#include <cuda_fp16.h>
#include <math.h>
#include <stdint.h>

// Problem constants
#define Bn 16384
#define Dn 1024
#define En 6
#define Hn 256
#define TMk 128
#define BD 16777216

// ---------------- device scratch ----------------
__device__ double g_load_sums[En];
__device__ int    g_expert_count[En];
__device__ int    g_expert_tok[En * Bn];   // token | (slot<<30)
__device__ float  g_expert_wt[En * Bn];
__device__ float  g_WrT[En * Dn];          // router weight transposed [e][d]
__device__ __half g_Xh[Bn * Dn];           // x hi (fp16)
__device__ __half g_Xl[Bn * Dn];           // x lo residual (fp16)
__device__ __half g_W1T[En * Hn * Dn];     // [e][h][d]  (K-major, n=h)
__device__ __half g_W2T[En * Dn * Hn];     // [e][d][h]  (K-major, n=d)
__device__ float  g_buf[2 * Bn * Dn];      // per-slot weighted expert outputs

// ---------------- helpers ----------------
__device__ __forceinline__ uint32_t smem_u32(const void* p) {
    uint32_t a;
    asm("{ .reg .u64 t; cvta.to.shared.u64 t, %1; cvt.u32.u64 %0, t; }" : "=r"(a) : "l"(p));
    return a;
}
__device__ __forceinline__ uint32_t sw(uint32_t o) { return o ^ ((o >> 3) & 0x70); }
__device__ __forceinline__ uint32_t pkh(__half a, __half b) {
    uint16_t lo = *(uint16_t*)&a, hi = *(uint16_t*)&b;
    return (uint32_t)lo | ((uint32_t)hi << 16);
}
__device__ __forceinline__ void ldsm4(uint32_t* r, uint32_t a) {
    asm volatile("ldmatrix.sync.aligned.m8n8.x4.shared.b16 {%0,%1,%2,%3}, [%4];"
                 : "=r"(r[0]), "=r"(r[1]), "=r"(r[2]), "=r"(r[3]) : "r"(a));
}
__device__ __forceinline__ void mma_h(float* c, const uint32_t* a, uint32_t b0, uint32_t b1) {
    asm volatile(
        "mma.sync.aligned.m16n8k16.row.col.f32.f16.f16.f32 "
        "{%0,%1,%2,%3}, {%4,%5,%6,%7}, {%8,%9}, {%0,%1,%2,%3};"
        : "+f"(c[0]), "+f"(c[1]), "+f"(c[2]), "+f"(c[3])
        : "r"(a[0]), "r"(a[1]), "r"(a[2]), "r"(a[3]), "r"(b0), "r"(b1));
}
__device__ __forceinline__ void cpa(uint32_t dst, const void* src) {
    asm volatile("cp.async.cg.shared.global [%0], [%1], 16;" :: "r"(dst), "l"(src));
}
__device__ __forceinline__ void cp_commit() { asm volatile("cp.async.commit_group;"); }
__device__ __forceinline__ void cp_wait0()  { asm volatile("cp.async.wait_group 0;"); }
__device__ __forceinline__ void cp_wait1()  { asm volatile("cp.async.wait_group 1;"); }
__device__ __forceinline__ float gelu(float t) {
    return 0.5f * t * (1.0f + erff(t * 0.70710678118654752f));
}

// ---------------- kernel: zero counters + transpose Wr ----------------
__global__ void prep_small(const float* __restrict__ Wr) {
    int i = blockIdx.x * 256 + threadIdx.x;
    if (i < En) {
        g_load_sums[i] = 0.0;
        g_expert_count[i] = 0;
    }
    if (i < Dn * En) {
        int d = i / En, e = i % En;
        g_WrT[e * Dn + d] = Wr[i];
    }
}

// ---------------- kernel: weight transpose -> fp16 ----------------
// src[e][R][C] fp32 -> dst[e][C][R] fp16
__global__ void transpose_half_kernel(const float* __restrict__ src, int R, int C, int which) {
    __shared__ float tile[32][33];
    int e = blockIdx.z;
    int c0 = blockIdx.x * 32, r0 = blockIdx.y * 32;
    const float* s = src + (size_t)e * R * C;
    __half* d = (which == 0 ? g_W1T : g_W2T) + (size_t)e * R * C;
#pragma unroll
    for (int i = 0; i < 32; i += 8)
        tile[threadIdx.y + i][threadIdx.x] = s[(size_t)(r0 + threadIdx.y + i) * C + c0 + threadIdx.x];
    __syncthreads();
#pragma unroll
    for (int i = 0; i < 32; i += 8) {
        size_t o = (size_t)(c0 + threadIdx.y + i) * R + r0 + threadIdx.x;
        d[o] = __float2half_rn(tile[threadIdx.x][threadIdx.y + i]);
    }
}

// ---------------- kernel: fused router + x split ----------------
// One warp per token: reads x row ONCE (float4), reads WrT[e] rows as
// coalesced float4 (L2/L1-hot, 24KB total), computes logits, softmax,
// top-2, list push, AND writes x hi/lo fp16.
__global__ void router_split_kernel(const float* __restrict__ x,
                                    const float* __restrict__ br) {
    __shared__ double s_load[En];
    int warp = threadIdx.x >> 5;
    int lane = threadIdx.x & 31;
    if (threadIdx.x < En) s_load[threadIdx.x] = 0.0;
    __syncthreads();

    int t = blockIdx.x * 8 + warp;
    {
        float acc[En];
#pragma unroll
        for (int e = 0; e < En; e++) acc[e] = 0.0f;
        const float* xr = x + (size_t)t * Dn;
        char* dh = (char*)g_Xh + (size_t)t * Dn * 2;
        char* dl = (char*)g_Xl + (size_t)t * Dn * 2;
#pragma unroll
        for (int jj = 0; jj < 8; jj++) {
            int d0 = (lane + 32 * jj) * 4;
            float4 v = *(const float4*)(xr + d0);
            // logits: 6 coalesced float4 reads of WrT (hot in L1/L2)
#pragma unroll
            for (int e = 0; e < En; e++) {
                float4 w = *(const float4*)(g_WrT + e * Dn + d0);
                acc[e] = fmaf(v.x, w.x, acc[e]);
                acc[e] = fmaf(v.y, w.y, acc[e]);
                acc[e] = fmaf(v.z, w.z, acc[e]);
                acc[e] = fmaf(v.w, w.w, acc[e]);
            }
            // split to fp16 hi/lo
            __half h0 = __float2half_rn(v.x), h1 = __float2half_rn(v.y);
            __half h2 = __float2half_rn(v.z), h3 = __float2half_rn(v.w);
            __half l0 = __float2half_rn(v.x - __half2float(h0));
            __half l1 = __float2half_rn(v.y - __half2float(h1));
            __half l2 = __float2half_rn(v.z - __half2float(h2));
            __half l3 = __float2half_rn(v.w - __half2float(h3));
            *(uint2*)(dh + d0 * 2) = make_uint2(pkh(h0, h1), pkh(h2, h3));
            *(uint2*)(dl + d0 * 2) = make_uint2(pkh(l0, l1), pkh(l2, l3));
        }
#pragma unroll
        for (int off = 16; off > 0; off >>= 1)
#pragma unroll
            for (int e = 0; e < En; e++)
                acc[e] += __shfl_xor_sync(0xffffffffu, acc[e], off);

        if (lane == 0) {
            float p[En];
            float m = -1e30f;
#pragma unroll
            for (int e = 0; e < En; e++) { p[e] = acc[e] + br[e]; m = fmaxf(m, p[e]); }
            float s = 0.0f;
#pragma unroll
            for (int e = 0; e < En; e++) { p[e] = expf(p[e] - m); s += p[e]; }
            float inv = 1.0f / s;
#pragma unroll
            for (int e = 0; e < En; e++)
                p[e] = 0.9f * p[e] * inv + (0.1f / 6.0f);
#pragma unroll
            for (int e = 0; e < En; e++)
                atomicAdd(&s_load[e], (double)p[e]);

            int i0 = 0;
#pragma unroll
            for (int e = 1; e < En; e++) if (p[e] > p[i0]) i0 = e;
            int i1 = (i0 == 0) ? 1 : 0;
#pragma unroll
            for (int e = 0; e < En; e++) if (e != i0 && p[e] > p[i1]) i1 = e;

            int pos0 = atomicAdd(&g_expert_count[i0], 1);
            g_expert_tok[i0 * Bn + pos0] = t;
            g_expert_wt[i0 * Bn + pos0] = p[i0];
            int pos1 = atomicAdd(&g_expert_count[i1], 1);
            g_expert_tok[i1 * Bn + pos1] = t | (1 << 30);
            g_expert_wt[i1 * Bn + pos1] = p[i1];
        }
    }
    __syncthreads();
    if (threadIdx.x < En)
        atomicAdd(&g_load_sums[threadIdx.x], s_load[threadIdx.x]);
}

// ---------------- kernel: aux scalar ----------------
__global__ void aux_kernel(float* __restrict__ out_aux) {
    double aux = 0.0;
#pragma unroll
    for (int e = 0; e < En; e++) {
        double load = g_load_sums[e] / (double)Bn;
        aux += load * log(load * (double)En + 1e-9);
    }
    out_aux[0] = (float)(aux / log((double)En + 1e-9));
}

// ---------------- kernel: expert MLP, fp16 2-term (exact-A-split, fp16 W) ----------------
// Arena (160KB, from 1KB-aligned base):
//  GEMM1 buf b at b*65536: Xh+0(16K) Xl+16384(16K) W+32768(32K)
//  Between GEMMs: Hh 4 panels of 16K at 0..65535; Hl at 65536..131071
//  GEMM2 W2 buf b at 131072 + b*16384 (16K each)
#define ARENA_BYTES (163840 + 1024)
extern __shared__ char dsm[];

__global__ void __launch_bounds__(512, 1) expert_kernel(
    const float* __restrict__ b1g, const float* __restrict__ b2g)
{
    __shared__ int   toks[TMk];
    __shared__ int   tslot[TMk];
    __shared__ float twt[TMk];
    __shared__ float b1s[Hn];
    __shared__ float b2s[Dn];

    int e = blockIdx.y;
    int cnt = g_expert_count[e];
    int base = blockIdx.x * TMk;
    if (base >= cnt) return;

    int tid = threadIdx.x;
    int wid = tid >> 5, lane = tid & 31;

    uint32_t raw = smem_u32(dsm);
    uint32_t sb  = (raw + 1023u) & ~1023u;
    char* arena  = dsm + (sb - raw);

    if (tid < TMk) {
        int i = base + tid;
        if (i < cnt) {
            int v = g_expert_tok[e * Bn + i];
            toks[tid] = v & 0x3FFFFFFF; tslot[tid] = v >> 30;
            twt[tid] = g_expert_wt[e * Bn + i];
        } else { toks[tid] = 0; tslot[tid] = 0; twt[tid] = 0.0f; }
    }
    if (tid < Hn) b1s[tid] = b1g[e * Hn + tid];
    for (int f = tid; f < Dn; f += 512) b2s[f] = b2g[e * Dn + f];
    __syncthreads();

    // ---- fragment address constants ----
    int g  = lane >> 3, r = lane & 7;
    int arow = (g & 1) * 8 + r, akoff = (g >> 1) * 16;
    int brow = (g >> 1) * 8 + r, bkoff = (g & 1) * 16;
    int warpM = wid & 3, warpN = wid >> 2;

    uint32_t aoff[2];
    aoff[0] = (uint32_t)(warpM * 32 + arow) * 128 + akoff;
    aoff[1] = aoff[0] + 16 * 128;
    uint32_t boff1[4];
#pragma unroll
    for (int j2 = 0; j2 < 4; j2++)
        boff1[j2] = (uint32_t)(warpN * 64 + j2 * 16 + brow) * 128 + bkoff;

    // ---- staging tables ----
    const char* srcXh[2]; const char* srcXl[2]; uint32_t dstX[2];
#pragma unroll
    for (int p = 0; p < 2; p++) {
        int f = tid + p * 512, row = f >> 3, seg = f & 7;
        srcXh[p] = (const char*)(g_Xh + (size_t)toks[row] * Dn) + seg * 16;
        srcXl[p] = (const char*)(g_Xl + (size_t)toks[row] * Dn) + seg * 16;
        dstX[p]  = sw((uint32_t)row * 128 + seg * 16);
    }
    const __half* W1t = g_W1T + (size_t)e * Hn * Dn;
    const char* srcW[4]; uint32_t dstW[4];
#pragma unroll
    for (int p = 0; p < 4; p++) {
        int f = tid + p * 512, row = f >> 3, seg = f & 7;
        srcW[p] = (const char*)(W1t + (size_t)row * Dn) + seg * 16;
        dstW[p] = sw((uint32_t)row * 128 + seg * 16);
    }

    auto stage1 = [&](int ci, uint32_t bb) {
        uint32_t o = (uint32_t)ci * 128;
#pragma unroll
        for (int p = 0; p < 2; p++) {
            cpa(bb + dstX[p],         srcXh[p] + o);
            cpa(bb + 16384 + dstX[p], srcXl[p] + o);
        }
#pragma unroll
        for (int p = 0; p < 4; p++)
            cpa(bb + 32768 + dstW[p], srcW[p] + o);
    };

    // ================= GEMM1: C1[128x256] = X[128x1024] @ W1 (2-term) =================
    float acc[2][8][4];
#pragma unroll
    for (int i = 0; i < 2; i++)
#pragma unroll
        for (int j = 0; j < 8; j++)
#pragma unroll
            for (int q = 0; q < 4; q++) acc[i][j][q] = 0.0f;

    uint32_t buf0 = sb, buf1 = sb + 65536;
    stage1(0, buf0); cp_commit();

    for (int ci = 0; ci < 16; ci++) {
        uint32_t cb = (ci & 1) ? buf1 : buf0;
        if (ci < 15) { stage1(ci + 1, (ci & 1) ? buf0 : buf1); cp_commit(); cp_wait1(); }
        else cp_wait0();
        __syncthreads();

        uint32_t xh = cb, xl = cb + 16384, wh = cb + 32768;
#pragma unroll
        for (int ks = 0; ks < 4; ks++) {
            uint32_t Ah[2][4], Al[2][4];
#pragma unroll
            for (int i = 0; i < 2; i++) {
                ldsm4(Ah[i], xh + sw(aoff[i] + ks * 32));
                ldsm4(Al[i], xl + sw(aoff[i] + ks * 32));
            }
#pragma unroll
            for (int j2 = 0; j2 < 4; j2++) {
                uint32_t Bh[4];
                ldsm4(Bh, wh + sw(boff1[j2] + ks * 32));
#pragma unroll
                for (int i = 0; i < 2; i++) {
                    mma_h(acc[i][2 * j2],     Ah[i], Bh[0], Bh[1]);
                    mma_h(acc[i][2 * j2 + 1], Ah[i], Bh[2], Bh[3]);
                    mma_h(acc[i][2 * j2],     Al[i], Bh[0], Bh[1]);
                    mma_h(acc[i][2 * j2 + 1], Al[i], Bh[2], Bh[3]);
                }
            }
        }
        __syncthreads();
    }

    // ---- prefetch first GEMM2 W2 stage (targets 131072+, no overlap with H) ----
    const __half* W2t = g_W2T + (size_t)e * Dn * Hn;
    uint32_t srcO2[2], dst2[2];
#pragma unroll
    for (int p = 0; p < 2; p++) {
        int f = tid + p * 512, row = f >> 3, seg = f & 7;
        srcO2[p] = (uint32_t)row * 512 + seg * 16;
        dst2[p]  = sw((uint32_t)row * 128 + seg * 16);
    }
    auto stage2 = [&](int it, uint32_t bb) {
        int np = it >> 2, kc = it & 3;
        uint32_t o = (uint32_t)np * 65536 + (uint32_t)kc * 128;
#pragma unroll
        for (int p = 0; p < 2; p++)
            cpa(bb + dst2[p], (const char*)W2t + srcO2[p] + o);
    };
    uint32_t w2b0 = sb + 131072, w2b1 = sb + 147456;
    stage2(0, w2b0); cp_commit();

    // ---- epilogue 1: bias + GELU + fp16 split -> H panels in smem ----
    {
        int mb = warpM * 32, nb = warpN * 64;
#pragma unroll
        for (int i = 0; i < 2; i++)
#pragma unroll
            for (int j = 0; j < 8; j++) {
                int m0 = mb + i * 16 + (lane >> 2);
                int n0 = nb + j * 8 + (lane & 3) * 2;
                float bb0 = b1s[n0], bb1 = b1s[n0 + 1];
#pragma unroll
                for (int hr = 0; hr < 2; hr++) {
                    int m = m0 + hr * 8;
                    float v0 = gelu(acc[i][j][hr * 2]     + bb0);
                    float v1 = gelu(acc[i][j][hr * 2 + 1] + bb1);
                    __half h0 = __float2half_rn(v0);
                    __half h1 = __float2half_rn(v1);
                    __half l0 = __float2half_rn(v0 - __half2float(h0));
                    __half l1 = __float2half_rn(v1 - __half2float(h1));
                    uint32_t off = ((uint32_t)(n0 >> 6)) * 16384 + sw((uint32_t)m * 128 + (n0 & 63) * 2);
                    *(uint32_t*)(arena + off)         = pkh(h0, h1);
                    *(uint32_t*)(arena + 65536 + off) = pkh(l0, l1);
                }
            }
    }
    __syncthreads();

    // ================= GEMM2: out[128x1024] = H[128x256] @ W2 (2-term) =================
    uint32_t boff2[2];
#pragma unroll
    for (int j2 = 0; j2 < 2; j2++)
        boff2[j2] = (uint32_t)(warpN * 32 + j2 * 16 + brow) * 128 + bkoff;

    float acc2[2][4][4];

    for (int it = 0; it < 32; it++) {
        int np = it >> 2, kc = it & 3;
        uint32_t cb = (it & 1) ? w2b1 : w2b0;
        if (it < 31) { stage2(it + 1, (it & 1) ? w2b0 : w2b1); cp_commit(); cp_wait1(); }
        else cp_wait0();
        __syncthreads();

        if (kc == 0) {
#pragma unroll
            for (int i = 0; i < 2; i++)
#pragma unroll
                for (int j = 0; j < 4; j++)
#pragma unroll
                    for (int q = 0; q < 4; q++) acc2[i][j][q] = 0.0f;
        }

        uint32_t ah = sb + kc * 16384, al = sb + 65536 + kc * 16384;
#pragma unroll
        for (int ks = 0; ks < 4; ks++) {
            uint32_t Ah[2][4], Al[2][4];
#pragma unroll
            for (int i = 0; i < 2; i++) {
                ldsm4(Ah[i], ah + sw(aoff[i] + ks * 32));
                ldsm4(Al[i], al + sw(aoff[i] + ks * 32));
            }
#pragma unroll
            for (int j2 = 0; j2 < 2; j2++) {
                uint32_t Bh[4];
                ldsm4(Bh, cb + sw(boff2[j2] + ks * 32));
#pragma unroll
                for (int i = 0; i < 2; i++) {
                    mma_h(acc2[i][2 * j2],     Ah[i], Bh[0], Bh[1]);
                    mma_h(acc2[i][2 * j2 + 1], Ah[i], Bh[2], Bh[3]);
                    mma_h(acc2[i][2 * j2],     Al[i], Bh[0], Bh[1]);
                    mma_h(acc2[i][2 * j2 + 1], Al[i], Bh[2], Bh[3]);
                }
            }
        }

        if (kc == 3) {
            // epilogue 2: weighted bias-add, direct per-slot store (no atomics)
            int mb = warpM * 32, nb = warpN * 32;
#pragma unroll
            for (int i = 0; i < 2; i++)
#pragma unroll
                for (int j = 0; j < 4; j++) {
                    int m0 = mb + i * 16 + (lane >> 2);
                    int n0 = np * 128 + nb + j * 8 + (lane & 3) * 2;
                    float bb0 = b2s[n0], bb1 = b2s[n0 + 1];
#pragma unroll
                    for (int hr = 0; hr < 2; hr++) {
                        int m = m0 + hr * 8;
                        if (base + m < cnt) {
                            int   tok  = toks[m];
                            int   slot = tslot[m];
                            float wgt  = twt[m];
                            float2 o;
                            o.x = wgt * (acc2[i][j][hr * 2]     + bb0);
                            o.y = wgt * (acc2[i][j][hr * 2 + 1] + bb1);
                            *(float2*)(g_buf + (size_t)slot * BD + (size_t)tok * Dn + n0) = o;
                        }
                    }
                }
        }
        __syncthreads();
    }
}

// ---------------- kernel: combine the two slots ----------------
__global__ void combine_kernel(float* __restrict__ out) {
    size_t i = ((size_t)blockIdx.x * 512 + threadIdx.x) * 4;
    float4 a = *(const float4*)(g_buf + i);
    float4 b = *(const float4*)(g_buf + (size_t)BD + i);
    *(float4*)(out + i) = make_float4(a.x + b.x, a.y + b.y, a.z + b.z, a.w + b.w);
}

// ---------------- launch ----------------
extern "C" void kernel_launch(void* const* d_in, const int* in_sizes, int n_in,
                              void* d_out, int out_size) {
    const float* x  = (const float*)d_in[0];
    const float* Wr = (const float*)d_in[1];
    const float* br = (const float*)d_in[2];
    const float* W1 = (const float*)d_in[3];
    const float* b1 = (const float*)d_in[4];
    const float* W2 = (const float*)d_in[5];
    const float* b2 = (const float*)d_in[6];
    float* out = (float*)d_out;

    cudaFuncSetAttribute(expert_kernel,
                         cudaFuncAttributeMaxDynamicSharedMemorySize, ARENA_BYTES);

    prep_small<<<(Dn * En + 255) / 256, 256>>>(Wr);
    transpose_half_kernel<<<dim3(8, 32, En), dim3(32, 8)>>>(W1, Dn, Hn, 0);  // -> [e][h][d]
    transpose_half_kernel<<<dim3(32, 8, En), dim3(32, 8)>>>(W2, Hn, Dn, 1);  // -> [e][d][h]
    router_split_kernel<<<Bn / 8, 256>>>(x, br);
    if (out_size > BD)
        aux_kernel<<<1, 1>>>(out + (size_t)BD);
    expert_kernel<<<dim3(Bn / TMk, En), 512, ARENA_BYTES>>>(b1, b2);
    combine_kernel<<<BD / 2048, 512>>>(out);
}

// round 7
// speedup vs baseline: 4.5522x; 1.0970x over previous
#include <cuda_runtime.h>
#include <cuda_fp16.h>
#include <math.h>
#include <stdint.h>

// Problem constants
#define Bn 16384
#define Dn 1024
#define En 6
#define Hn 256
#define TMk 128
#define BD 16777216

// ---------------- device scratch ----------------
__device__ double g_load_sums[En];
__device__ int    g_expert_count[En];
__device__ int    g_expert_tok[En * Bn];   // token | (slot<<30)
__device__ float  g_expert_wt[En * Bn];
__device__ float  g_WrT[En * Dn];          // router weight transposed [e][d]
__device__ __half g_Xh[Bn * Dn];           // x hi (fp16)
__device__ __half g_Xl[Bn * Dn];           // x lo residual (fp16)
__device__ __half g_W1T[En * Hn * Dn];     // [e][h][d]  (K-major, n=h)
__device__ __half g_W2T[En * Dn * Hn];     // [e][d][h]  (K-major, n=d)
__device__ float  g_buf[2 * Bn * Dn];      // per-slot weighted expert outputs

// ---------------- helpers ----------------
__device__ __forceinline__ uint32_t smem_u32(const void* p) {
    uint32_t a;
    asm("{ .reg .u64 t; cvta.to.shared.u64 t, %1; cvt.u32.u64 %0, t; }" : "=r"(a) : "l"(p));
    return a;
}
__device__ __forceinline__ uint32_t sw(uint32_t o) { return o ^ ((o >> 3) & 0x70); }
__device__ __forceinline__ uint32_t pkh(__half a, __half b) {
    uint16_t lo = *(uint16_t*)&a, hi = *(uint16_t*)&b;
    return (uint32_t)lo | ((uint32_t)hi << 16);
}
__device__ __forceinline__ void ldsm4(uint32_t* r, uint32_t a) {
    asm volatile("ldmatrix.sync.aligned.m8n8.x4.shared.b16 {%0,%1,%2,%3}, [%4];"
                 : "=r"(r[0]), "=r"(r[1]), "=r"(r[2]), "=r"(r[3]) : "r"(a));
}
__device__ __forceinline__ void mma_h(float* c, const uint32_t* a, uint32_t b0, uint32_t b1) {
    asm volatile(
        "mma.sync.aligned.m16n8k16.row.col.f32.f16.f16.f32 "
        "{%0,%1,%2,%3}, {%4,%5,%6,%7}, {%8,%9}, {%0,%1,%2,%3};"
        : "+f"(c[0]), "+f"(c[1]), "+f"(c[2]), "+f"(c[3])
        : "r"(a[0]), "r"(a[1]), "r"(a[2]), "r"(a[3]), "r"(b0), "r"(b1));
}
__device__ __forceinline__ void cpa(uint32_t dst, const void* src) {
    asm volatile("cp.async.cg.shared.global [%0], [%1], 16;" :: "r"(dst), "l"(src));
}
__device__ __forceinline__ void cp_commit() { asm volatile("cp.async.commit_group;"); }
__device__ __forceinline__ void cp_wait0()  { asm volatile("cp.async.wait_group 0;"); }
__device__ __forceinline__ void cp_wait1()  { asm volatile("cp.async.wait_group 1;"); }
__device__ __forceinline__ float gelu(float t) {
    return 0.5f * t * (1.0f + erff(t * 0.70710678118654752f));
}

// ---------------- kernel: zero counters + transpose Wr ----------------
__global__ void prep_small(const float* __restrict__ Wr) {
    int i = blockIdx.x * 256 + threadIdx.x;
    if (i < En) {
        g_load_sums[i] = 0.0;
        g_expert_count[i] = 0;
    }
    if (i < Dn * En) {
        int d = i / En, e = i % En;
        g_WrT[e * Dn + d] = Wr[i];
    }
}

// ---------------- kernel: weight transpose -> fp16 ----------------
__global__ void transpose_half_kernel(const float* __restrict__ src, int R, int C, int which) {
    __shared__ float tile[32][33];
    int e = blockIdx.z;
    int c0 = blockIdx.x * 32, r0 = blockIdx.y * 32;
    const float* s = src + (size_t)e * R * C;
    __half* d = (which == 0 ? g_W1T : g_W2T) + (size_t)e * R * C;
#pragma unroll
    for (int i = 0; i < 32; i += 8)
        tile[threadIdx.y + i][threadIdx.x] = s[(size_t)(r0 + threadIdx.y + i) * C + c0 + threadIdx.x];
    __syncthreads();
#pragma unroll
    for (int i = 0; i < 32; i += 8) {
        size_t o = (size_t)(c0 + threadIdx.y + i) * R + r0 + threadIdx.x;
        d[o] = __float2half_rn(tile[threadIdx.x][threadIdx.y + i]);
    }
}

// ---------------- kernel: fused router + x split ----------------
__global__ void router_split_kernel(const float* __restrict__ x,
                                    const float* __restrict__ br) {
    __shared__ double s_load[En];
    int warp = threadIdx.x >> 5;
    int lane = threadIdx.x & 31;
    if (threadIdx.x < En) s_load[threadIdx.x] = 0.0;
    __syncthreads();

    int t = blockIdx.x * 8 + warp;
    {
        float acc[En];
#pragma unroll
        for (int e = 0; e < En; e++) acc[e] = 0.0f;
        const float* xr = x + (size_t)t * Dn;
        char* dh = (char*)g_Xh + (size_t)t * Dn * 2;
        char* dl = (char*)g_Xl + (size_t)t * Dn * 2;
#pragma unroll
        for (int jj = 0; jj < 8; jj++) {
            int d0 = (lane + 32 * jj) * 4;
            float4 v = *(const float4*)(xr + d0);
#pragma unroll
            for (int e = 0; e < En; e++) {
                float4 w = *(const float4*)(g_WrT + e * Dn + d0);
                acc[e] = fmaf(v.x, w.x, acc[e]);
                acc[e] = fmaf(v.y, w.y, acc[e]);
                acc[e] = fmaf(v.z, w.z, acc[e]);
                acc[e] = fmaf(v.w, w.w, acc[e]);
            }
            __half h0 = __float2half_rn(v.x), h1 = __float2half_rn(v.y);
            __half h2 = __float2half_rn(v.z), h3 = __float2half_rn(v.w);
            __half l0 = __float2half_rn(v.x - __half2float(h0));
            __half l1 = __float2half_rn(v.y - __half2float(h1));
            __half l2 = __float2half_rn(v.z - __half2float(h2));
            __half l3 = __float2half_rn(v.w - __half2float(h3));
            *(uint2*)(dh + d0 * 2) = make_uint2(pkh(h0, h1), pkh(h2, h3));
            *(uint2*)(dl + d0 * 2) = make_uint2(pkh(l0, l1), pkh(l2, l3));
        }
#pragma unroll
        for (int off = 16; off > 0; off >>= 1)
#pragma unroll
            for (int e = 0; e < En; e++)
                acc[e] += __shfl_xor_sync(0xffffffffu, acc[e], off);

        if (lane == 0) {
            float p[En];
            float m = -1e30f;
#pragma unroll
            for (int e = 0; e < En; e++) { p[e] = acc[e] + br[e]; m = fmaxf(m, p[e]); }
            float s = 0.0f;
#pragma unroll
            for (int e = 0; e < En; e++) { p[e] = expf(p[e] - m); s += p[e]; }
            float inv = 1.0f / s;
#pragma unroll
            for (int e = 0; e < En; e++)
                p[e] = 0.9f * p[e] * inv + (0.1f / 6.0f);
#pragma unroll
            for (int e = 0; e < En; e++)
                atomicAdd(&s_load[e], (double)p[e]);

            int i0 = 0;
#pragma unroll
            for (int e = 1; e < En; e++) if (p[e] > p[i0]) i0 = e;
            int i1 = (i0 == 0) ? 1 : 0;
#pragma unroll
            for (int e = 0; e < En; e++) if (e != i0 && p[e] > p[i1]) i1 = e;

            int pos0 = atomicAdd(&g_expert_count[i0], 1);
            g_expert_tok[i0 * Bn + pos0] = t;
            g_expert_wt[i0 * Bn + pos0] = p[i0];
            int pos1 = atomicAdd(&g_expert_count[i1], 1);
            g_expert_tok[i1 * Bn + pos1] = t | (1 << 30);
            g_expert_wt[i1 * Bn + pos1] = p[i1];
        }
    }
    __syncthreads();
    if (threadIdx.x < En)
        atomicAdd(&g_load_sums[threadIdx.x], s_load[threadIdx.x]);
}

// ---------------- kernel: aux scalar ----------------
__global__ void aux_kernel(float* __restrict__ out_aux) {
    double aux = 0.0;
#pragma unroll
    for (int e = 0; e < En; e++) {
        double load = g_load_sums[e] / (double)Bn;
        aux += load * log(load * (double)En + 1e-9);
    }
    out_aux[0] = (float)(aux / log((double)En + 1e-9));
}

// ---------------- kernel: expert MLP ----------------
// GEMM1: 2-term (Xh+Xl exact split) x fp16 W1.  GEMM2: 1-term fp16 H x fp16 W2.
// Arena (192KB + pad), 3-stage pipelines, ONE barrier per k-chunk:
//  GEMM1 bufs: B(c) = sb + 65536*(c%3): Xh+0(16K) Xl+16384(16K) W+32768(32K)
//  H panels (post-GEMM1): 4 x 16K at sb+0..65535 (old B0)
//  GEMM2 bufs: C(it) = sb + 65536 + 16384*(it%3)
#define ARENA_BYTES (196608 + 1024)
extern __shared__ char dsm[];

__global__ void __launch_bounds__(512, 1) expert_kernel(
    const float* __restrict__ b1g, const float* __restrict__ b2g)
{
    __shared__ int   toks[TMk];
    __shared__ int   tslot[TMk];
    __shared__ float twt[TMk];
    __shared__ float b1s[Hn];
    __shared__ float b2s[Dn];

    int e = blockIdx.y;
    int cnt = g_expert_count[e];
    int base = blockIdx.x * TMk;
    if (base >= cnt) return;

    int tid = threadIdx.x;
    int wid = tid >> 5, lane = tid & 31;

    uint32_t raw = smem_u32(dsm);
    uint32_t sb  = (raw + 1023u) & ~1023u;
    char* arena  = dsm + (sb - raw);

    if (tid < TMk) {
        int i = base + tid;
        if (i < cnt) {
            int v = g_expert_tok[e * Bn + i];
            toks[tid] = v & 0x3FFFFFFF; tslot[tid] = v >> 30;
            twt[tid] = g_expert_wt[e * Bn + i];
        } else { toks[tid] = 0; tslot[tid] = 0; twt[tid] = 0.0f; }
    }
    if (tid < Hn) b1s[tid] = b1g[e * Hn + tid];
    for (int f = tid; f < Dn; f += 512) b2s[f] = b2g[e * Dn + f];
    __syncthreads();

    // ---- fragment address constants ----
    int g  = lane >> 3, r = lane & 7;
    int arow = (g & 1) * 8 + r, akoff = (g >> 1) * 16;
    int brow = (g >> 1) * 8 + r, bkoff = (g & 1) * 16;
    int warpM = wid & 3, warpN = wid >> 2;

    uint32_t aoff[2];
    aoff[0] = (uint32_t)(warpM * 32 + arow) * 128 + akoff;
    aoff[1] = aoff[0] + 16 * 128;
    uint32_t boff1[4];
#pragma unroll
    for (int j2 = 0; j2 < 4; j2++)
        boff1[j2] = (uint32_t)(warpN * 64 + j2 * 16 + brow) * 128 + bkoff;

    // ---- staging tables ----
    const char* srcXh[2]; const char* srcXl[2]; uint32_t dstX[2];
#pragma unroll
    for (int p = 0; p < 2; p++) {
        int f = tid + p * 512, row = f >> 3, seg = f & 7;
        srcXh[p] = (const char*)(g_Xh + (size_t)toks[row] * Dn) + seg * 16;
        srcXl[p] = (const char*)(g_Xl + (size_t)toks[row] * Dn) + seg * 16;
        dstX[p]  = sw((uint32_t)row * 128 + seg * 16);
    }
    const __half* W1t = g_W1T + (size_t)e * Hn * Dn;
    const char* srcW[4]; uint32_t dstW[4];
#pragma unroll
    for (int p = 0; p < 4; p++) {
        int f = tid + p * 512, row = f >> 3, seg = f & 7;
        srcW[p] = (const char*)(W1t + (size_t)row * Dn) + seg * 16;
        dstW[p] = sw((uint32_t)row * 128 + seg * 16);
    }

    auto stage1 = [&](int ci, uint32_t bb) {
        uint32_t o = (uint32_t)ci * 128;
#pragma unroll
        for (int p = 0; p < 2; p++) {
            cpa(bb + dstX[p],         srcXh[p] + o);
            cpa(bb + 16384 + dstX[p], srcXl[p] + o);
        }
#pragma unroll
        for (int p = 0; p < 4; p++)
            cpa(bb + 32768 + dstW[p], srcW[p] + o);
    };

    // ================= GEMM1: C1[128x256] = X[128x1024] @ W1 (2-term, 3-stage) =========
    float acc[2][8][4];
#pragma unroll
    for (int i = 0; i < 2; i++)
#pragma unroll
        for (int j = 0; j < 8; j++)
#pragma unroll
            for (int q = 0; q < 4; q++) acc[i][j][q] = 0.0f;

    stage1(0, sb);         cp_commit();
    stage1(1, sb + 65536); cp_commit();

    for (int ci = 0; ci < 16; ci++) {
        if (ci == 15) cp_wait0(); else cp_wait1();
        __syncthreads();                       // buffer(ci) ready; readers of buffer(ci-1) done
        if (ci + 2 < 16) { stage1(ci + 2, sb + 65536u * ((ci + 2) % 3)); cp_commit(); }

        uint32_t cb = sb + 65536u * (ci % 3);
        uint32_t xh = cb, xl = cb + 16384, wh = cb + 32768;
#pragma unroll
        for (int ks = 0; ks < 4; ks++) {
            uint32_t Ah[2][4], Al[2][4];
#pragma unroll
            for (int i = 0; i < 2; i++) {
                ldsm4(Ah[i], xh + sw(aoff[i] + ks * 32));
                ldsm4(Al[i], xl + sw(aoff[i] + ks * 32));
            }
#pragma unroll
            for (int j2 = 0; j2 < 4; j2++) {
                uint32_t Bh[4];
                ldsm4(Bh, wh + sw(boff1[j2] + ks * 32));
#pragma unroll
                for (int i = 0; i < 2; i++) {
                    mma_h(acc[i][2 * j2],     Ah[i], Bh[0], Bh[1]);
                    mma_h(acc[i][2 * j2 + 1], Ah[i], Bh[2], Bh[3]);
                    mma_h(acc[i][2 * j2],     Al[i], Bh[0], Bh[1]);
                    mma_h(acc[i][2 * j2 + 1], Al[i], Bh[2], Bh[3]);
                }
            }
        }
    }
    __syncthreads();   // all GEMM1 reads done before H overwrites buffer-0 region

    // ---- prefetch first two GEMM2 W2 stages (region sb+65536.., free now) ----
    const __half* W2t = g_W2T + (size_t)e * Dn * Hn;
    uint32_t srcO2[2], dst2[2];
#pragma unroll
    for (int p = 0; p < 2; p++) {
        int f = tid + p * 512, row = f >> 3, seg = f & 7;
        srcO2[p] = (uint32_t)row * 512 + seg * 16;
        dst2[p]  = sw((uint32_t)row * 128 + seg * 16);
    }
    auto stage2 = [&](int it, uint32_t bb) {
        int np = it >> 2, kc = it & 3;
        uint32_t o = (uint32_t)np * 65536 + (uint32_t)kc * 128;
#pragma unroll
        for (int p = 0; p < 2; p++)
            cpa(bb + dst2[p], (const char*)W2t + srcO2[p] + o);
    };
    stage2(0, sb + 65536);         cp_commit();
    stage2(1, sb + 65536 + 16384); cp_commit();

    // ---- epilogue 1: bias + GELU -> fp16 H panels (single term) ----
    {
        int mb = warpM * 32, nb = warpN * 64;
#pragma unroll
        for (int i = 0; i < 2; i++)
#pragma unroll
            for (int j = 0; j < 8; j++) {
                int m0 = mb + i * 16 + (lane >> 2);
                int n0 = nb + j * 8 + (lane & 3) * 2;
                float bb0 = b1s[n0], bb1 = b1s[n0 + 1];
#pragma unroll
                for (int hr = 0; hr < 2; hr++) {
                    int m = m0 + hr * 8;
                    float v0 = gelu(acc[i][j][hr * 2]     + bb0);
                    float v1 = gelu(acc[i][j][hr * 2 + 1] + bb1);
                    uint32_t off = ((uint32_t)(n0 >> 6)) * 16384 + sw((uint32_t)m * 128 + (n0 & 63) * 2);
                    *(uint32_t*)(arena + off) = pkh(__float2half_rn(v0), __float2half_rn(v1));
                }
            }
    }

    // ================= GEMM2: out[128x1024] = H[128x256] @ W2 (1-term, 3-stage) =========
    uint32_t boff2[2];
#pragma unroll
    for (int j2 = 0; j2 < 2; j2++)
        boff2[j2] = (uint32_t)(warpN * 32 + j2 * 16 + brow) * 128 + bkoff;

    float acc2[2][4][4];

    for (int it = 0; it < 32; it++) {
        int np = it >> 2, kc = it & 3;
        if (it == 31) cp_wait0(); else cp_wait1();
        __syncthreads();                       // buffer(it) ready; H writes visible (it=0)
        if (it + 2 < 32) { stage2(it + 2, sb + 65536 + 16384u * ((it + 2) % 3)); cp_commit(); }

        if (kc == 0) {
#pragma unroll
            for (int i = 0; i < 2; i++)
#pragma unroll
                for (int j = 0; j < 4; j++)
#pragma unroll
                    for (int q = 0; q < 4; q++) acc2[i][j][q] = 0.0f;
        }

        uint32_t ah = sb + kc * 16384;
        uint32_t cb = sb + 65536 + 16384u * (it % 3);
#pragma unroll
        for (int ks = 0; ks < 4; ks++) {
            uint32_t Ah[2][4];
#pragma unroll
            for (int i = 0; i < 2; i++)
                ldsm4(Ah[i], ah + sw(aoff[i] + ks * 32));
#pragma unroll
            for (int j2 = 0; j2 < 2; j2++) {
                uint32_t Bh[4];
                ldsm4(Bh, cb + sw(boff2[j2] + ks * 32));
#pragma unroll
                for (int i = 0; i < 2; i++) {
                    mma_h(acc2[i][2 * j2],     Ah[i], Bh[0], Bh[1]);
                    mma_h(acc2[i][2 * j2 + 1], Ah[i], Bh[2], Bh[3]);
                }
            }
        }

        if (kc == 3) {
            int mb = warpM * 32, nb = warpN * 32;
#pragma unroll
            for (int i = 0; i < 2; i++)
#pragma unroll
                for (int j = 0; j < 4; j++) {
                    int m0 = mb + i * 16 + (lane >> 2);
                    int n0 = np * 128 + nb + j * 8 + (lane & 3) * 2;
                    float bb0 = b2s[n0], bb1 = b2s[n0 + 1];
#pragma unroll
                    for (int hr = 0; hr < 2; hr++) {
                        int m = m0 + hr * 8;
                        if (base + m < cnt) {
                            int   tok  = toks[m];
                            int   slot = tslot[m];
                            float wgt  = twt[m];
                            float2 o;
                            o.x = wgt * (acc2[i][j][hr * 2]     + bb0);
                            o.y = wgt * (acc2[i][j][hr * 2 + 1] + bb1);
                            *(float2*)(g_buf + (size_t)slot * BD + (size_t)tok * Dn + n0) = o;
                        }
                    }
                }
        }
    }
}

// ---------------- kernel: combine the two slots ----------------
__global__ void combine_kernel(float* __restrict__ out) {
    size_t i = ((size_t)blockIdx.x * 512 + threadIdx.x) * 4;
    float4 a = *(const float4*)(g_buf + i);
    float4 b = *(const float4*)(g_buf + (size_t)BD + i);
    *(float4*)(out + i) = make_float4(a.x + b.x, a.y + b.y, a.z + b.z, a.w + b.w);
}

// ---------------- launch ----------------
extern "C" void kernel_launch(void* const* d_in, const int* in_sizes, int n_in,
                              void* d_out, int out_size) {
    const float* x  = (const float*)d_in[0];
    const float* Wr = (const float*)d_in[1];
    const float* br = (const float*)d_in[2];
    const float* W1 = (const float*)d_in[3];
    const float* b1 = (const float*)d_in[4];
    const float* W2 = (const float*)d_in[5];
    const float* b2 = (const float*)d_in[6];
    float* out = (float*)d_out;

    cudaFuncSetAttribute(expert_kernel,
                         cudaFuncAttributeMaxDynamicSharedMemorySize, ARENA_BYTES);

    prep_small<<<(Dn * En + 255) / 256, 256>>>(Wr);
    transpose_half_kernel<<<dim3(8, 32, En), dim3(32, 8)>>>(W1, Dn, Hn, 0);  // -> [e][h][d]
    transpose_half_kernel<<<dim3(32, 8, En), dim3(32, 8)>>>(W2, Hn, Dn, 1);  // -> [e][d][h]
    router_split_kernel<<<Bn / 8, 256>>>(x, br);
    if (out_size > BD)
        aux_kernel<<<1, 1>>>(out + (size_t)BD);
    expert_kernel<<<dim3(Bn / TMk, En), 512, ARENA_BYTES>>>(b1, b2);
    combine_kernel<<<BD / 2048, 512>>>(out);
}

// round 8
// speedup vs baseline: 5.6589x; 1.2431x over previous
#include <cuda_runtime.h>
#include <cuda_fp16.h>
#include <math.h>
#include <stdint.h>

// Problem constants
#define Bn 16384
#define Dn 1024
#define En 6
#define Hn 256
#define TMk 128
#define BD 16777216

// ---------------- device scratch ----------------
__device__ double g_load_sums[En];
__device__ int    g_expert_count[En];
__device__ int    g_expert_tok[En * Bn];   // token | (slot<<30)
__device__ float  g_expert_wt[En * Bn];
__device__ float  g_WrT[En * Dn];          // router weight transposed [e][d]
__device__ __half g_Xh[Bn * Dn];           // x (fp16)
__device__ __half g_W1T[En * Hn * Dn];     // [e][h][d]  (K-major, n=h)
__device__ __half g_W2T[En * Dn * Hn];     // [e][d][h]  (K-major, n=d)
__device__ float  g_buf[Bn * Dn];          // slot-1 weighted expert outputs

// ---------------- helpers ----------------
__device__ __forceinline__ uint32_t smem_u32(const void* p) {
    uint32_t a;
    asm("{ .reg .u64 t; cvta.to.shared.u64 t, %1; cvt.u32.u64 %0, t; }" : "=r"(a) : "l"(p));
    return a;
}
__device__ __forceinline__ uint32_t sw(uint32_t o) { return o ^ ((o >> 3) & 0x70); }
__device__ __forceinline__ uint32_t pkh(__half a, __half b) {
    uint16_t lo = *(uint16_t*)&a, hi = *(uint16_t*)&b;
    return (uint32_t)lo | ((uint32_t)hi << 16);
}
__device__ __forceinline__ void ldsm4(uint32_t* r, uint32_t a) {
    asm volatile("ldmatrix.sync.aligned.m8n8.x4.shared.b16 {%0,%1,%2,%3}, [%4];"
                 : "=r"(r[0]), "=r"(r[1]), "=r"(r[2]), "=r"(r[3]) : "r"(a));
}
__device__ __forceinline__ void mma_h(float* c, const uint32_t* a, uint32_t b0, uint32_t b1) {
    asm volatile(
        "mma.sync.aligned.m16n8k16.row.col.f32.f16.f16.f32 "
        "{%0,%1,%2,%3}, {%4,%5,%6,%7}, {%8,%9}, {%0,%1,%2,%3};"
        : "+f"(c[0]), "+f"(c[1]), "+f"(c[2]), "+f"(c[3])
        : "r"(a[0]), "r"(a[1]), "r"(a[2]), "r"(a[3]), "r"(b0), "r"(b1));
}
__device__ __forceinline__ void cpa(uint32_t dst, const void* src) {
    asm volatile("cp.async.cg.shared.global [%0], [%1], 16;" :: "r"(dst), "l"(src));
}
__device__ __forceinline__ void cp_commit() { asm volatile("cp.async.commit_group;"); }
__device__ __forceinline__ void cp_wait0()  { asm volatile("cp.async.wait_group 0;"); }
__device__ __forceinline__ void cp_wait1()  { asm volatile("cp.async.wait_group 1;"); }
__device__ __forceinline__ float gelu(float t) {
    return 0.5f * t * (1.0f + erff(t * 0.70710678118654752f));
}

// ---------------- kernel: zero counters + transpose Wr ----------------
__global__ void prep_small(const float* __restrict__ Wr) {
    int i = blockIdx.x * 256 + threadIdx.x;
    if (i < En) {
        g_load_sums[i] = 0.0;
        g_expert_count[i] = 0;
    }
    if (i < Dn * En) {
        int d = i / En, e = i % En;
        g_WrT[e * Dn + d] = Wr[i];
    }
}

// ---------------- kernel: weight transpose -> fp16 ----------------
__global__ void transpose_half_kernel(const float* __restrict__ src, int R, int C, int which) {
    __shared__ float tile[32][33];
    int e = blockIdx.z;
    int c0 = blockIdx.x * 32, r0 = blockIdx.y * 32;
    const float* s = src + (size_t)e * R * C;
    __half* d = (which == 0 ? g_W1T : g_W2T) + (size_t)e * R * C;
#pragma unroll
    for (int i = 0; i < 32; i += 8)
        tile[threadIdx.y + i][threadIdx.x] = s[(size_t)(r0 + threadIdx.y + i) * C + c0 + threadIdx.x];
    __syncthreads();
#pragma unroll
    for (int i = 0; i < 32; i += 8) {
        size_t o = (size_t)(c0 + threadIdx.y + i) * R + r0 + threadIdx.x;
        d[o] = __float2half_rn(tile[threadIdx.x][threadIdx.y + i]);
    }
}

// ---------------- kernel: fused router + x->fp16 ----------------
__global__ void router_split_kernel(const float* __restrict__ x,
                                    const float* __restrict__ br) {
    __shared__ double s_load[En];
    int warp = threadIdx.x >> 5;
    int lane = threadIdx.x & 31;
    if (threadIdx.x < En) s_load[threadIdx.x] = 0.0;
    __syncthreads();

    int t = blockIdx.x * 8 + warp;
    {
        float acc[En];
#pragma unroll
        for (int e = 0; e < En; e++) acc[e] = 0.0f;
        const float* xr = x + (size_t)t * Dn;
        char* dh = (char*)g_Xh + (size_t)t * Dn * 2;
#pragma unroll
        for (int jj = 0; jj < 8; jj++) {
            int d0 = (lane + 32 * jj) * 4;
            float4 v = *(const float4*)(xr + d0);
#pragma unroll
            for (int e = 0; e < En; e++) {
                float4 w = *(const float4*)(g_WrT + e * Dn + d0);
                acc[e] = fmaf(v.x, w.x, acc[e]);
                acc[e] = fmaf(v.y, w.y, acc[e]);
                acc[e] = fmaf(v.z, w.z, acc[e]);
                acc[e] = fmaf(v.w, w.w, acc[e]);
            }
            *(uint2*)(dh + d0 * 2) = make_uint2(
                pkh(__float2half_rn(v.x), __float2half_rn(v.y)),
                pkh(__float2half_rn(v.z), __float2half_rn(v.w)));
        }
#pragma unroll
        for (int off = 16; off > 0; off >>= 1)
#pragma unroll
            for (int e = 0; e < En; e++)
                acc[e] += __shfl_xor_sync(0xffffffffu, acc[e], off);

        if (lane == 0) {
            float p[En];
            float m = -1e30f;
#pragma unroll
            for (int e = 0; e < En; e++) { p[e] = acc[e] + br[e]; m = fmaxf(m, p[e]); }
            float s = 0.0f;
#pragma unroll
            for (int e = 0; e < En; e++) { p[e] = expf(p[e] - m); s += p[e]; }
            float inv = 1.0f / s;
#pragma unroll
            for (int e = 0; e < En; e++)
                p[e] = 0.9f * p[e] * inv + (0.1f / 6.0f);
#pragma unroll
            for (int e = 0; e < En; e++)
                atomicAdd(&s_load[e], (double)p[e]);

            int i0 = 0;
#pragma unroll
            for (int e = 1; e < En; e++) if (p[e] > p[i0]) i0 = e;
            int i1 = (i0 == 0) ? 1 : 0;
#pragma unroll
            for (int e = 0; e < En; e++) if (e != i0 && p[e] > p[i1]) i1 = e;

            int pos0 = atomicAdd(&g_expert_count[i0], 1);
            g_expert_tok[i0 * Bn + pos0] = t;
            g_expert_wt[i0 * Bn + pos0] = p[i0];
            int pos1 = atomicAdd(&g_expert_count[i1], 1);
            g_expert_tok[i1 * Bn + pos1] = t | (1 << 30);
            g_expert_wt[i1 * Bn + pos1] = p[i1];
        }
    }
    __syncthreads();
    if (threadIdx.x < En)
        atomicAdd(&g_load_sums[threadIdx.x], s_load[threadIdx.x]);
}

// ---------------- kernel: aux scalar ----------------
__global__ void aux_kernel(float* __restrict__ out_aux) {
    double aux = 0.0;
#pragma unroll
    for (int e = 0; e < En; e++) {
        double load = g_load_sums[e] / (double)Bn;
        aux += load * log(load * (double)En + 1e-9);
    }
    out_aux[0] = (float)(aux / log((double)En + 1e-9));
}

// ---------------- kernel: expert MLP (pure fp16 MMA, fp32 accum) ----------------
// Arena (144KB + pad), 3-stage pipelines, ONE barrier per k-chunk:
//  GEMM1 bufs: B(c) = sb + 49152*(c%3): Xh+0(16K) W+16384(32K)
//  H panels (post-GEMM1): 4 x 16K at sb+0..65535
//  GEMM2 bufs: C(it) = sb + 65536 + 16384*(it%3)
#define ARENA_BYTES (147456 + 1024)
extern __shared__ char dsm[];

__global__ void __launch_bounds__(512, 1) expert_kernel(
    const float* __restrict__ b1g, const float* __restrict__ b2g,
    float* __restrict__ out)
{
    __shared__ int   toks[TMk];
    __shared__ int   tslot[TMk];
    __shared__ float twt[TMk];
    __shared__ float b1s[Hn];
    __shared__ float b2s[Dn];

    int e = blockIdx.y;
    int cnt = g_expert_count[e];
    int base = blockIdx.x * TMk;
    if (base >= cnt) return;

    int tid = threadIdx.x;
    int wid = tid >> 5, lane = tid & 31;

    uint32_t raw = smem_u32(dsm);
    uint32_t sb  = (raw + 1023u) & ~1023u;
    char* arena  = dsm + (sb - raw);

    if (tid < TMk) {
        int i = base + tid;
        if (i < cnt) {
            int v = g_expert_tok[e * Bn + i];
            toks[tid] = v & 0x3FFFFFFF; tslot[tid] = v >> 30;
            twt[tid] = g_expert_wt[e * Bn + i];
        } else { toks[tid] = 0; tslot[tid] = 0; twt[tid] = 0.0f; }
    }
    if (tid < Hn) b1s[tid] = b1g[e * Hn + tid];
    for (int f = tid; f < Dn; f += 512) b2s[f] = b2g[e * Dn + f];
    __syncthreads();

    // ---- fragment address constants ----
    int g  = lane >> 3, r = lane & 7;
    int arow = (g & 1) * 8 + r, akoff = (g >> 1) * 16;
    int brow = (g >> 1) * 8 + r, bkoff = (g & 1) * 16;
    int warpM = wid & 3, warpN = wid >> 2;

    uint32_t aoff[2];
    aoff[0] = (uint32_t)(warpM * 32 + arow) * 128 + akoff;
    aoff[1] = aoff[0] + 16 * 128;
    uint32_t boff1[4];
#pragma unroll
    for (int j2 = 0; j2 < 4; j2++)
        boff1[j2] = (uint32_t)(warpN * 64 + j2 * 16 + brow) * 128 + bkoff;

    // ---- staging tables ----
    const char* srcX[2]; uint32_t dstX[2];
#pragma unroll
    for (int p = 0; p < 2; p++) {
        int f = tid + p * 512, row = f >> 3, seg = f & 7;
        srcX[p] = (const char*)(g_Xh + (size_t)toks[row] * Dn) + seg * 16;
        dstX[p] = sw((uint32_t)row * 128 + seg * 16);
    }
    const __half* W1t = g_W1T + (size_t)e * Hn * Dn;
    const char* srcW[4]; uint32_t dstW[4];
#pragma unroll
    for (int p = 0; p < 4; p++) {
        int f = tid + p * 512, row = f >> 3, seg = f & 7;
        srcW[p] = (const char*)(W1t + (size_t)row * Dn) + seg * 16;
        dstW[p] = sw((uint32_t)row * 128 + seg * 16);
    }

    auto stage1 = [&](int ci, uint32_t bb) {
        uint32_t o = (uint32_t)ci * 128;
#pragma unroll
        for (int p = 0; p < 2; p++)
            cpa(bb + dstX[p], srcX[p] + o);
#pragma unroll
        for (int p = 0; p < 4; p++)
            cpa(bb + 16384 + dstW[p], srcW[p] + o);
    };

    // ================= GEMM1: C1[128x256] = X[128x1024] @ W1 (1-term, 3-stage) =========
    float acc[2][8][4];
#pragma unroll
    for (int i = 0; i < 2; i++)
#pragma unroll
        for (int j = 0; j < 8; j++)
#pragma unroll
            for (int q = 0; q < 4; q++) acc[i][j][q] = 0.0f;

    stage1(0, sb);         cp_commit();
    stage1(1, sb + 49152); cp_commit();

    for (int ci = 0; ci < 16; ci++) {
        if (ci == 15) cp_wait0(); else cp_wait1();
        __syncthreads();
        if (ci + 2 < 16) { stage1(ci + 2, sb + 49152u * ((ci + 2) % 3)); cp_commit(); }

        uint32_t cb = sb + 49152u * (ci % 3);
        uint32_t xh = cb, wh = cb + 16384;
#pragma unroll
        for (int ks = 0; ks < 4; ks++) {
            uint32_t Ah[2][4];
#pragma unroll
            for (int i = 0; i < 2; i++)
                ldsm4(Ah[i], xh + sw(aoff[i] + ks * 32));
#pragma unroll
            for (int j2 = 0; j2 < 4; j2++) {
                uint32_t Bh[4];
                ldsm4(Bh, wh + sw(boff1[j2] + ks * 32));
#pragma unroll
                for (int i = 0; i < 2; i++) {
                    mma_h(acc[i][2 * j2],     Ah[i], Bh[0], Bh[1]);
                    mma_h(acc[i][2 * j2 + 1], Ah[i], Bh[2], Bh[3]);
                }
            }
        }
    }
    __syncthreads();   // all GEMM1 reads done before H overwrites arena

    // ---- prefetch first two GEMM2 W2 stages (region sb+65536.., free now) ----
    const __half* W2t = g_W2T + (size_t)e * Dn * Hn;
    uint32_t srcO2[2], dst2[2];
#pragma unroll
    for (int p = 0; p < 2; p++) {
        int f = tid + p * 512, row = f >> 3, seg = f & 7;
        srcO2[p] = (uint32_t)row * 512 + seg * 16;
        dst2[p]  = sw((uint32_t)row * 128 + seg * 16);
    }
    auto stage2 = [&](int it, uint32_t bb) {
        int np = it >> 2, kc = it & 3;
        uint32_t o = (uint32_t)np * 65536 + (uint32_t)kc * 128;
#pragma unroll
        for (int p = 0; p < 2; p++)
            cpa(bb + dst2[p], (const char*)W2t + srcO2[p] + o);
    };
    stage2(0, sb + 65536);         cp_commit();
    stage2(1, sb + 65536 + 16384); cp_commit();

    // ---- epilogue 1: bias + GELU -> fp16 H panels ----
    {
        int mb = warpM * 32, nb = warpN * 64;
#pragma unroll
        for (int i = 0; i < 2; i++)
#pragma unroll
            for (int j = 0; j < 8; j++) {
                int m0 = mb + i * 16 + (lane >> 2);
                int n0 = nb + j * 8 + (lane & 3) * 2;
                float bb0 = b1s[n0], bb1 = b1s[n0 + 1];
#pragma unroll
                for (int hr = 0; hr < 2; hr++) {
                    int m = m0 + hr * 8;
                    float v0 = gelu(acc[i][j][hr * 2]     + bb0);
                    float v1 = gelu(acc[i][j][hr * 2 + 1] + bb1);
                    uint32_t off = ((uint32_t)(n0 >> 6)) * 16384 + sw((uint32_t)m * 128 + (n0 & 63) * 2);
                    *(uint32_t*)(arena + off) = pkh(__float2half_rn(v0), __float2half_rn(v1));
                }
            }
    }

    // ================= GEMM2: out[128x1024] = H[128x256] @ W2 (1-term, 3-stage) =========
    uint32_t boff2[2];
#pragma unroll
    for (int j2 = 0; j2 < 2; j2++)
        boff2[j2] = (uint32_t)(warpN * 32 + j2 * 16 + brow) * 128 + bkoff;

    float acc2[2][4][4];

    for (int it = 0; it < 32; it++) {
        int np = it >> 2, kc = it & 3;
        if (it == 31) cp_wait0(); else cp_wait1();
        __syncthreads();
        if (it + 2 < 32) { stage2(it + 2, sb + 65536 + 16384u * ((it + 2) % 3)); cp_commit(); }

        if (kc == 0) {
#pragma unroll
            for (int i = 0; i < 2; i++)
#pragma unroll
                for (int j = 0; j < 4; j++)
#pragma unroll
                    for (int q = 0; q < 4; q++) acc2[i][j][q] = 0.0f;
        }

        uint32_t ah = sb + kc * 16384;
        uint32_t cb = sb + 65536 + 16384u * (it % 3);
#pragma unroll
        for (int ks = 0; ks < 4; ks++) {
            uint32_t Ah[2][4];
#pragma unroll
            for (int i = 0; i < 2; i++)
                ldsm4(Ah[i], ah + sw(aoff[i] + ks * 32));
#pragma unroll
            for (int j2 = 0; j2 < 2; j2++) {
                uint32_t Bh[4];
                ldsm4(Bh, cb + sw(boff2[j2] + ks * 32));
#pragma unroll
                for (int i = 0; i < 2; i++) {
                    mma_h(acc2[i][2 * j2],     Ah[i], Bh[0], Bh[1]);
                    mma_h(acc2[i][2 * j2 + 1], Ah[i], Bh[2], Bh[3]);
                }
            }
        }

        if (kc == 3) {
            // epilogue 2: weighted bias-add; slot0 -> out directly, slot1 -> g_buf
            int mb = warpM * 32, nb = warpN * 32;
#pragma unroll
            for (int i = 0; i < 2; i++)
#pragma unroll
                for (int j = 0; j < 4; j++) {
                    int m0 = mb + i * 16 + (lane >> 2);
                    int n0 = np * 128 + nb + j * 8 + (lane & 3) * 2;
                    float bb0 = b2s[n0], bb1 = b2s[n0 + 1];
#pragma unroll
                    for (int hr = 0; hr < 2; hr++) {
                        int m = m0 + hr * 8;
                        if (base + m < cnt) {
                            int   tok  = toks[m];
                            float wgt  = twt[m];
                            float* dst = (tslot[m] == 0 ? out : g_buf) + (size_t)tok * Dn + n0;
                            float2 o;
                            o.x = wgt * (acc2[i][j][hr * 2]     + bb0);
                            o.y = wgt * (acc2[i][j][hr * 2 + 1] + bb1);
                            *(float2*)dst = o;
                        }
                    }
                }
        }
    }
}

// ---------------- kernel: add slot-1 buffer into out ----------------
__global__ void combine_kernel(float* __restrict__ out) {
    size_t i = ((size_t)blockIdx.x * 512 + threadIdx.x) * 4;
    float4 a = *(const float4*)(out + i);
    float4 b = *(const float4*)(g_buf + i);
    *(float4*)(out + i) = make_float4(a.x + b.x, a.y + b.y, a.z + b.z, a.w + b.w);
}

// ---------------- launch ----------------
extern "C" void kernel_launch(void* const* d_in, const int* in_sizes, int n_in,
                              void* d_out, int out_size) {
    const float* x  = (const float*)d_in[0];
    const float* Wr = (const float*)d_in[1];
    const float* br = (const float*)d_in[2];
    const float* W1 = (const float*)d_in[3];
    const float* b1 = (const float*)d_in[4];
    const float* W2 = (const float*)d_in[5];
    const float* b2 = (const float*)d_in[6];
    float* out = (float*)d_out;

    cudaFuncSetAttribute(expert_kernel,
                         cudaFuncAttributeMaxDynamicSharedMemorySize, ARENA_BYTES);

    prep_small<<<(Dn * En + 255) / 256, 256>>>(Wr);
    transpose_half_kernel<<<dim3(8, 32, En), dim3(32, 8)>>>(W1, Dn, Hn, 0);  // -> [e][h][d]
    transpose_half_kernel<<<dim3(32, 8, En), dim3(32, 8)>>>(W2, Hn, Dn, 1);  // -> [e][d][h]
    router_split_kernel<<<Bn / 8, 256>>>(x, br);
    if (out_size > BD)
        aux_kernel<<<1, 1>>>(out + (size_t)BD);
    expert_kernel<<<dim3(Bn / TMk, En), 512, ARENA_BYTES>>>(b1, b2, out);
    combine_kernel<<<BD / 2048, 512>>>(out);
}

// round 9
// speedup vs baseline: 5.8588x; 1.0353x over previous
#include <cuda_runtime.h>
#include <cuda_fp16.h>
#include <math.h>
#include <stdint.h>

// Problem constants
#define Bn 16384
#define Dn 1024
#define En 6
#define Hn 256
#define TMk 128
#define BD 16777216

// ---------------- device scratch ----------------
__device__ double g_load_sums[En];
__device__ int    g_expert_count[En];
__device__ int    g_expert_tok[En * Bn];   // token | (slot<<30)
__device__ float  g_expert_wt[En * Bn];
__device__ float  g_WrT[En * Dn];          // router weight transposed [e][d]
__device__ __half g_Xh[Bn * Dn];           // x (fp16)
__device__ __half g_W1T[En * Hn * Dn];     // [e][h][d]  (K-major, n=h)
__device__ __half g_W2T[En * Dn * Hn];     // [e][d][h]  (K-major, n=d)
__device__ __half g_bufh[2u * Bn * Dn];    // per-slot weighted expert outputs (fp16)

// ---------------- helpers ----------------
__device__ __forceinline__ uint32_t smem_u32(const void* p) {
    uint32_t a;
    asm("{ .reg .u64 t; cvta.to.shared.u64 t, %1; cvt.u32.u64 %0, t; }" : "=r"(a) : "l"(p));
    return a;
}
__device__ __forceinline__ uint32_t sw(uint32_t o) { return o ^ ((o >> 3) & 0x70); }
__device__ __forceinline__ uint32_t pkh(__half a, __half b) {
    uint16_t lo = *(uint16_t*)&a, hi = *(uint16_t*)&b;
    return (uint32_t)lo | ((uint32_t)hi << 16);
}
__device__ __forceinline__ void ldsm4(uint32_t* r, uint32_t a) {
    asm volatile("ldmatrix.sync.aligned.m8n8.x4.shared.b16 {%0,%1,%2,%3}, [%4];"
                 : "=r"(r[0]), "=r"(r[1]), "=r"(r[2]), "=r"(r[3]) : "r"(a));
}
__device__ __forceinline__ void mma_h(float* c, const uint32_t* a, uint32_t b0, uint32_t b1) {
    asm volatile(
        "mma.sync.aligned.m16n8k16.row.col.f32.f16.f16.f32 "
        "{%0,%1,%2,%3}, {%4,%5,%6,%7}, {%8,%9}, {%0,%1,%2,%3};"
        : "+f"(c[0]), "+f"(c[1]), "+f"(c[2]), "+f"(c[3])
        : "r"(a[0]), "r"(a[1]), "r"(a[2]), "r"(a[3]), "r"(b0), "r"(b1));
}
__device__ __forceinline__ void cpa(uint32_t dst, const void* src) {
    asm volatile("cp.async.cg.shared.global [%0], [%1], 16;" :: "r"(dst), "l"(src));
}
__device__ __forceinline__ void cp_commit() { asm volatile("cp.async.commit_group;"); }
__device__ __forceinline__ void cp_wait0()  { asm volatile("cp.async.wait_group 0;"); }
__device__ __forceinline__ void cp_wait1()  { asm volatile("cp.async.wait_group 1;"); }
__device__ __forceinline__ void cp_wait2()  { asm volatile("cp.async.wait_group 2;"); }
__device__ __forceinline__ float gelu(float t) {
    return 0.5f * t * (1.0f + erff(t * 0.70710678118654752f));
}

// ---------------- kernel: zero counters + transpose Wr ----------------
__global__ void prep_small(const float* __restrict__ Wr) {
    int i = blockIdx.x * 256 + threadIdx.x;
    if (i < En) {
        g_load_sums[i] = 0.0;
        g_expert_count[i] = 0;
    }
    if (i < Dn * En) {
        int d = i / En, e = i % En;
        g_WrT[e * Dn + d] = Wr[i];
    }
}

// ---------------- kernel: weight transpose -> fp16 ----------------
__global__ void transpose_half_kernel(const float* __restrict__ src, int R, int C, int which) {
    __shared__ float tile[32][33];
    int e = blockIdx.z;
    int c0 = blockIdx.x * 32, r0 = blockIdx.y * 32;
    const float* s = src + (size_t)e * R * C;
    __half* d = (which == 0 ? g_W1T : g_W2T) + (size_t)e * R * C;
#pragma unroll
    for (int i = 0; i < 32; i += 8)
        tile[threadIdx.y + i][threadIdx.x] = s[(size_t)(r0 + threadIdx.y + i) * C + c0 + threadIdx.x];
    __syncthreads();
#pragma unroll
    for (int i = 0; i < 32; i += 8) {
        size_t o = (size_t)(c0 + threadIdx.y + i) * R + r0 + threadIdx.x;
        d[o] = __float2half_rn(tile[threadIdx.x][threadIdx.y + i]);
    }
}

// ---------------- kernel: fused router + x->fp16 ----------------
// One warp per token. All 8 float4 x-loads issued back-to-back (MLP=8),
// then logits FMAs + fp16 convert/store.
__global__ void router_split_kernel(const float* __restrict__ x,
                                    const float* __restrict__ br) {
    __shared__ double s_load[En];
    int warp = threadIdx.x >> 5;
    int lane = threadIdx.x & 31;
    if (threadIdx.x < En) s_load[threadIdx.x] = 0.0;
    __syncthreads();

    int t = blockIdx.x * 8 + warp;
    {
        const float* xr = x + (size_t)t * Dn;
        char* dh = (char*)g_Xh + (size_t)t * Dn * 2;

        float4 v[8];
#pragma unroll
        for (int jj = 0; jj < 8; jj++)
            v[jj] = *(const float4*)(xr + (lane + 32 * jj) * 4);

        float acc[En];
#pragma unroll
        for (int e = 0; e < En; e++) acc[e] = 0.0f;
#pragma unroll
        for (int jj = 0; jj < 8; jj++) {
            int d0 = (lane + 32 * jj) * 4;
#pragma unroll
            for (int e = 0; e < En; e++) {
                float4 w = *(const float4*)(g_WrT + e * Dn + d0);
                acc[e] = fmaf(v[jj].x, w.x, acc[e]);
                acc[e] = fmaf(v[jj].y, w.y, acc[e]);
                acc[e] = fmaf(v[jj].z, w.z, acc[e]);
                acc[e] = fmaf(v[jj].w, w.w, acc[e]);
            }
            *(uint2*)(dh + d0 * 2) = make_uint2(
                pkh(__float2half_rn(v[jj].x), __float2half_rn(v[jj].y)),
                pkh(__float2half_rn(v[jj].z), __float2half_rn(v[jj].w)));
        }
#pragma unroll
        for (int off = 16; off > 0; off >>= 1)
#pragma unroll
            for (int e = 0; e < En; e++)
                acc[e] += __shfl_xor_sync(0xffffffffu, acc[e], off);

        if (lane == 0) {
            float p[En];
            float m = -1e30f;
#pragma unroll
            for (int e = 0; e < En; e++) { p[e] = acc[e] + br[e]; m = fmaxf(m, p[e]); }
            float s = 0.0f;
#pragma unroll
            for (int e = 0; e < En; e++) { p[e] = expf(p[e] - m); s += p[e]; }
            float inv = 1.0f / s;
#pragma unroll
            for (int e = 0; e < En; e++)
                p[e] = 0.9f * p[e] * inv + (0.1f / 6.0f);
#pragma unroll
            for (int e = 0; e < En; e++)
                atomicAdd(&s_load[e], (double)p[e]);

            int i0 = 0;
#pragma unroll
            for (int e = 1; e < En; e++) if (p[e] > p[i0]) i0 = e;
            int i1 = (i0 == 0) ? 1 : 0;
#pragma unroll
            for (int e = 0; e < En; e++) if (e != i0 && p[e] > p[i1]) i1 = e;

            int pos0 = atomicAdd(&g_expert_count[i0], 1);
            g_expert_tok[i0 * Bn + pos0] = t;
            g_expert_wt[i0 * Bn + pos0] = p[i0];
            int pos1 = atomicAdd(&g_expert_count[i1], 1);
            g_expert_tok[i1 * Bn + pos1] = t | (1 << 30);
            g_expert_wt[i1 * Bn + pos1] = p[i1];
        }
    }
    __syncthreads();
    if (threadIdx.x < En)
        atomicAdd(&g_load_sums[threadIdx.x], s_load[threadIdx.x]);
}

// ---------------- kernel: aux scalar ----------------
__global__ void aux_kernel(float* __restrict__ out_aux) {
    double aux = 0.0;
#pragma unroll
    for (int e = 0; e < En; e++) {
        double load = g_load_sums[e] / (double)Bn;
        aux += load * log(load * (double)En + 1e-9);
    }
    out_aux[0] = (float)(aux / log((double)En + 1e-9));
}

// ---------------- kernel: expert MLP (pure fp16 MMA, fp32 accum) ----------------
// Arena (144KB + pad):
//  GEMM1 (3-stage): B(c) = sb + 49152*(c%3): Xh+0(16K) W+16384(32K)
//  H panels (post-GEMM1): 4 x 16K at sb+0..65535
//  GEMM2 (4-stage): C(it) = sb + 65536 + 16384*(it%4)
#define ARENA_BYTES (147456 + 1024)
extern __shared__ char dsm[];

__global__ void __launch_bounds__(512, 1) expert_kernel(
    const float* __restrict__ b1g, const float* __restrict__ b2g)
{
    __shared__ int   toks[TMk];
    __shared__ int   tslot[TMk];
    __shared__ float twt[TMk];
    __shared__ float b1s[Hn];
    __shared__ float b2s[Dn];

    int e = blockIdx.y;
    int cnt = g_expert_count[e];
    int base = blockIdx.x * TMk;
    if (base >= cnt) return;

    int tid = threadIdx.x;
    int wid = tid >> 5, lane = tid & 31;

    uint32_t raw = smem_u32(dsm);
    uint32_t sb  = (raw + 1023u) & ~1023u;
    char* arena  = dsm + (sb - raw);

    if (tid < TMk) {
        int i = base + tid;
        if (i < cnt) {
            int v = g_expert_tok[e * Bn + i];
            toks[tid] = v & 0x3FFFFFFF; tslot[tid] = v >> 30;
            twt[tid] = g_expert_wt[e * Bn + i];
        } else { toks[tid] = 0; tslot[tid] = 0; twt[tid] = 0.0f; }
    }
    if (tid < Hn) b1s[tid] = b1g[e * Hn + tid];
    for (int f = tid; f < Dn; f += 512) b2s[f] = b2g[e * Dn + f];
    __syncthreads();

    // ---- fragment address constants ----
    int g  = lane >> 3, r = lane & 7;
    int arow = (g & 1) * 8 + r, akoff = (g >> 1) * 16;
    int brow = (g >> 1) * 8 + r, bkoff = (g & 1) * 16;
    int warpM = wid & 3, warpN = wid >> 2;

    uint32_t aoff[2];
    aoff[0] = (uint32_t)(warpM * 32 + arow) * 128 + akoff;
    aoff[1] = aoff[0] + 16 * 128;
    uint32_t boff1[4];
#pragma unroll
    for (int j2 = 0; j2 < 4; j2++)
        boff1[j2] = (uint32_t)(warpN * 64 + j2 * 16 + brow) * 128 + bkoff;

    // ---- staging tables ----
    const char* srcX[2]; uint32_t dstX[2];
#pragma unroll
    for (int p = 0; p < 2; p++) {
        int f = tid + p * 512, row = f >> 3, seg = f & 7;
        srcX[p] = (const char*)(g_Xh + (size_t)toks[row] * Dn) + seg * 16;
        dstX[p] = sw((uint32_t)row * 128 + seg * 16);
    }
    const __half* W1t = g_W1T + (size_t)e * Hn * Dn;
    const char* srcW[4]; uint32_t dstW[4];
#pragma unroll
    for (int p = 0; p < 4; p++) {
        int f = tid + p * 512, row = f >> 3, seg = f & 7;
        srcW[p] = (const char*)(W1t + (size_t)row * Dn) + seg * 16;
        dstW[p] = sw((uint32_t)row * 128 + seg * 16);
    }

    auto stage1 = [&](int ci, uint32_t bb) {
        uint32_t o = (uint32_t)ci * 128;
#pragma unroll
        for (int p = 0; p < 2; p++)
            cpa(bb + dstX[p], srcX[p] + o);
#pragma unroll
        for (int p = 0; p < 4; p++)
            cpa(bb + 16384 + dstW[p], srcW[p] + o);
    };

    // ================= GEMM1: C1[128x256] = X[128x1024] @ W1 (3-stage) =========
    float acc[2][8][4];
#pragma unroll
    for (int i = 0; i < 2; i++)
#pragma unroll
        for (int j = 0; j < 8; j++)
#pragma unroll
            for (int q = 0; q < 4; q++) acc[i][j][q] = 0.0f;

    stage1(0, sb);         cp_commit();
    stage1(1, sb + 49152); cp_commit();

    for (int ci = 0; ci < 16; ci++) {
        if (ci == 15) cp_wait0(); else cp_wait1();
        __syncthreads();
        if (ci + 2 < 16) { stage1(ci + 2, sb + 49152u * ((ci + 2) % 3)); cp_commit(); }

        uint32_t cb = sb + 49152u * (ci % 3);
        uint32_t xh = cb, wh = cb + 16384;
#pragma unroll
        for (int ks = 0; ks < 4; ks++) {
            uint32_t Ah[2][4];
#pragma unroll
            for (int i = 0; i < 2; i++)
                ldsm4(Ah[i], xh + sw(aoff[i] + ks * 32));
#pragma unroll
            for (int j2 = 0; j2 < 4; j2++) {
                uint32_t Bh[4];
                ldsm4(Bh, wh + sw(boff1[j2] + ks * 32));
#pragma unroll
                for (int i = 0; i < 2; i++) {
                    mma_h(acc[i][2 * j2],     Ah[i], Bh[0], Bh[1]);
                    mma_h(acc[i][2 * j2 + 1], Ah[i], Bh[2], Bh[3]);
                }
            }
        }
    }
    __syncthreads();   // all GEMM1 reads done before H overwrites arena

    // ---- prefetch first three GEMM2 W2 stages (region sb+65536.., free now) ----
    const __half* W2t = g_W2T + (size_t)e * Dn * Hn;
    uint32_t srcO2[2], dst2[2];
#pragma unroll
    for (int p = 0; p < 2; p++) {
        int f = tid + p * 512, row = f >> 3, seg = f & 7;
        srcO2[p] = (uint32_t)row * 512 + seg * 16;
        dst2[p]  = sw((uint32_t)row * 128 + seg * 16);
    }
    auto stage2 = [&](int it, uint32_t bb) {
        int np = it >> 2, kc = it & 3;
        uint32_t o = (uint32_t)np * 65536 + (uint32_t)kc * 128;
#pragma unroll
        for (int p = 0; p < 2; p++)
            cpa(bb + dst2[p], (const char*)W2t + srcO2[p] + o);
    };
    stage2(0, sb + 65536);             cp_commit();
    stage2(1, sb + 65536 + 16384);     cp_commit();
    stage2(2, sb + 65536 + 32768);     cp_commit();

    // ---- epilogue 1: bias + GELU -> fp16 H panels ----
    {
        int mb = warpM * 32, nb = warpN * 64;
#pragma unroll
        for (int i = 0; i < 2; i++)
#pragma unroll
            for (int j = 0; j < 8; j++) {
                int m0 = mb + i * 16 + (lane >> 2);
                int n0 = nb + j * 8 + (lane & 3) * 2;
                float bb0 = b1s[n0], bb1 = b1s[n0 + 1];
#pragma unroll
                for (int hr = 0; hr < 2; hr++) {
                    int m = m0 + hr * 8;
                    float v0 = gelu(acc[i][j][hr * 2]     + bb0);
                    float v1 = gelu(acc[i][j][hr * 2 + 1] + bb1);
                    uint32_t off = ((uint32_t)(n0 >> 6)) * 16384 + sw((uint32_t)m * 128 + (n0 & 63) * 2);
                    *(uint32_t*)(arena + off) = pkh(__float2half_rn(v0), __float2half_rn(v1));
                }
            }
    }

    // ================= GEMM2: out[128x1024] = H[128x256] @ W2 (4-stage) =========
    uint32_t boff2[2];
#pragma unroll
    for (int j2 = 0; j2 < 2; j2++)
        boff2[j2] = (uint32_t)(warpN * 32 + j2 * 16 + brow) * 128 + bkoff;

    float acc2[2][4][4];

    for (int it = 0; it < 32; it++) {
        int np = it >> 2, kc = it & 3;
        if (it < 30) cp_wait2(); else if (it == 30) cp_wait1(); else cp_wait0();
        __syncthreads();
        if (it + 3 < 32) { stage2(it + 3, sb + 65536 + 16384u * ((it + 3) % 4)); cp_commit(); }

        if (kc == 0) {
#pragma unroll
            for (int i = 0; i < 2; i++)
#pragma unroll
                for (int j = 0; j < 4; j++)
#pragma unroll
                    for (int q = 0; q < 4; q++) acc2[i][j][q] = 0.0f;
        }

        uint32_t ah = sb + kc * 16384;
        uint32_t cb = sb + 65536 + 16384u * (it % 4);
#pragma unroll
        for (int ks = 0; ks < 4; ks++) {
            uint32_t Ah[2][4];
#pragma unroll
            for (int i = 0; i < 2; i++)
                ldsm4(Ah[i], ah + sw(aoff[i] + ks * 32));
#pragma unroll
            for (int j2 = 0; j2 < 2; j2++) {
                uint32_t Bh[4];
                ldsm4(Bh, cb + sw(boff2[j2] + ks * 32));
#pragma unroll
                for (int i = 0; i < 2; i++) {
                    mma_h(acc2[i][2 * j2],     Ah[i], Bh[0], Bh[1]);
                    mma_h(acc2[i][2 * j2 + 1], Ah[i], Bh[2], Bh[3]);
                }
            }
        }

        if (kc == 3) {
            // epilogue 2: weighted bias-add -> per-slot fp16 buffer
            int mb = warpM * 32, nb = warpN * 32;
#pragma unroll
            for (int i = 0; i < 2; i++)
#pragma unroll
                for (int j = 0; j < 4; j++) {
                    int m0 = mb + i * 16 + (lane >> 2);
                    int n0 = np * 128 + nb + j * 8 + (lane & 3) * 2;
                    float bb0 = b2s[n0], bb1 = b2s[n0 + 1];
#pragma unroll
                    for (int hr = 0; hr < 2; hr++) {
                        int m = m0 + hr * 8;
                        if (base + m < cnt) {
                            int   tok  = toks[m];
                            float wgt  = twt[m];
                            float o0 = wgt * (acc2[i][j][hr * 2]     + bb0);
                            float o1 = wgt * (acc2[i][j][hr * 2 + 1] + bb1);
                            uint32_t* dst = (uint32_t*)((char*)g_bufh +
                                ((size_t)tslot[m] * BD + (size_t)tok * Dn + n0) * 2);
                            *dst = pkh(__float2half_rn(o0), __float2half_rn(o1));
                        }
                    }
                }
        }
    }
}

// ---------------- kernel: combine the two fp16 slots -> fp32 out ----------------
__global__ void combine_kernel(float* __restrict__ out) {
    size_t i = ((size_t)blockIdx.x * 512 + threadIdx.x) * 4;
    uint2 pa = *(const uint2*)((const char*)g_bufh + i * 2);
    uint2 pb = *(const uint2*)((const char*)g_bufh + ((size_t)BD + i) * 2);
    __half2 a0 = *(__half2*)&pa.x, a1 = *(__half2*)&pa.y;
    __half2 b0 = *(__half2*)&pb.x, b1 = *(__half2*)&pb.y;
    float2 fa0 = __half22float2(a0), fa1 = __half22float2(a1);
    float2 fb0 = __half22float2(b0), fb1 = __half22float2(b1);
    *(float4*)(out + i) = make_float4(fa0.x + fb0.x, fa0.y + fb0.y,
                                      fa1.x + fb1.x, fa1.y + fb1.y);
}

// ---------------- launch ----------------
extern "C" void kernel_launch(void* const* d_in, const int* in_sizes, int n_in,
                              void* d_out, int out_size) {
    const float* x  = (const float*)d_in[0];
    const float* Wr = (const float*)d_in[1];
    const float* br = (const float*)d_in[2];
    const float* W1 = (const float*)d_in[3];
    const float* b1 = (const float*)d_in[4];
    const float* W2 = (const float*)d_in[5];
    const float* b2 = (const float*)d_in[6];
    float* out = (float*)d_out;

    cudaFuncSetAttribute(expert_kernel,
                         cudaFuncAttributeMaxDynamicSharedMemorySize, ARENA_BYTES);

    prep_small<<<(Dn * En + 255) / 256, 256>>>(Wr);
    transpose_half_kernel<<<dim3(8, 32, En), dim3(32, 8)>>>(W1, Dn, Hn, 0);  // -> [e][h][d]
    transpose_half_kernel<<<dim3(32, 8, En), dim3(32, 8)>>>(W2, Hn, Dn, 1);  // -> [e][d][h]
    router_split_kernel<<<Bn / 8, 256>>>(x, br);
    if (out_size > BD)
        aux_kernel<<<1, 1>>>(out + (size_t)BD);
    expert_kernel<<<dim3(Bn / TMk, En), 512, ARENA_BYTES>>>(b1, b2);
    combine_kernel<<<BD / 2048, 512>>>(out);
}

// round 10
// speedup vs baseline: 6.0824x; 1.0382x over previous
#include <cuda_runtime.h>
#include <cuda_fp16.h>
#include <math.h>
#include <stdint.h>

// Problem constants
#define Bn 16384
#define Dn 1024
#define En 6
#define Hn 256
#define TMk 128
#define BD 16777216

// ---------------- device scratch ----------------
__device__ double g_load_sums[En];
__device__ int    g_expert_count[En];
__device__ int    g_expert_tok[En * Bn];   // token | (slot<<30)
__device__ float  g_expert_wt[En * Bn];
__device__ float  g_WrT[En * Dn];          // router weight transposed [e][d]
__device__ __half g_Xh[Bn * Dn];           // x (fp16)
__device__ __half g_W1T[En * Hn * Dn];     // [e][h][d]  (K-major, n=h)
__device__ __half g_W2T[En * Dn * Hn];     // [e][d][h]  (K-major, n=d)
__device__ __half g_bufh[2u * Bn * Dn];    // per-slot weighted expert outputs (fp16)

// ---------------- helpers ----------------
__device__ __forceinline__ uint32_t smem_u32(const void* p) {
    uint32_t a;
    asm("{ .reg .u64 t; cvta.to.shared.u64 t, %1; cvt.u32.u64 %0, t; }" : "=r"(a) : "l"(p));
    return a;
}
__device__ __forceinline__ uint32_t sw(uint32_t o) { return o ^ ((o >> 3) & 0x70); }
__device__ __forceinline__ uint32_t pkh(__half a, __half b) {
    uint16_t lo = *(uint16_t*)&a, hi = *(uint16_t*)&b;
    return (uint32_t)lo | ((uint32_t)hi << 16);
}
__device__ __forceinline__ void ldsm4(uint32_t* r, uint32_t a) {
    asm volatile("ldmatrix.sync.aligned.m8n8.x4.shared.b16 {%0,%1,%2,%3}, [%4];"
                 : "=r"(r[0]), "=r"(r[1]), "=r"(r[2]), "=r"(r[3]) : "r"(a));
}
__device__ __forceinline__ void mma_h(float* c, const uint32_t* a, uint32_t b0, uint32_t b1) {
    asm volatile(
        "mma.sync.aligned.m16n8k16.row.col.f32.f16.f16.f32 "
        "{%0,%1,%2,%3}, {%4,%5,%6,%7}, {%8,%9}, {%0,%1,%2,%3};"
        : "+f"(c[0]), "+f"(c[1]), "+f"(c[2]), "+f"(c[3])
        : "r"(a[0]), "r"(a[1]), "r"(a[2]), "r"(a[3]), "r"(b0), "r"(b1));
}
__device__ __forceinline__ void cpa(uint32_t dst, const void* src) {
    asm volatile("cp.async.cg.shared.global [%0], [%1], 16;" :: "r"(dst), "l"(src));
}
__device__ __forceinline__ void cp_commit() { asm volatile("cp.async.commit_group;"); }
__device__ __forceinline__ void cp_wait0()  { asm volatile("cp.async.wait_group 0;"); }
__device__ __forceinline__ void cp_wait1()  { asm volatile("cp.async.wait_group 1;"); }
__device__ __forceinline__ void cp_wait2()  { asm volatile("cp.async.wait_group 2;"); }
__device__ __forceinline__ float gelu(float t) {
    return 0.5f * t * (1.0f + erff(t * 0.70710678118654752f));
}

// ---------------- kernel: zero counters + transpose Wr ----------------
__global__ void prep_small(const float* __restrict__ Wr) {
    int i = blockIdx.x * 256 + threadIdx.x;
    if (i < En) {
        g_load_sums[i] = 0.0;
        g_expert_count[i] = 0;
    }
    if (i < Dn * En) {
        int d = i / En, e = i % En;
        g_WrT[e * Dn + d] = Wr[i];
    }
}

// ---------------- kernel: weight transpose -> fp16 ----------------
__global__ void transpose_half_kernel(const float* __restrict__ src, int R, int C, int which) {
    __shared__ float tile[32][33];
    int e = blockIdx.z;
    int c0 = blockIdx.x * 32, r0 = blockIdx.y * 32;
    const float* s = src + (size_t)e * R * C;
    __half* d = (which == 0 ? g_W1T : g_W2T) + (size_t)e * R * C;
#pragma unroll
    for (int i = 0; i < 32; i += 8)
        tile[threadIdx.y + i][threadIdx.x] = s[(size_t)(r0 + threadIdx.y + i) * C + c0 + threadIdx.x];
    __syncthreads();
#pragma unroll
    for (int i = 0; i < 32; i += 8) {
        size_t o = (size_t)(c0 + threadIdx.y + i) * R + r0 + threadIdx.x;
        d[o] = __float2half_rn(tile[threadIdx.x][threadIdx.y + i]);
    }
}

// ---------------- kernel: fused router + x->fp16 ----------------
// One warp per token; WrT staged in shared memory (LDS instead of LDG);
// 8-deep x-load batch (reg cap 64 via launch_bounds).
__global__ void __launch_bounds__(256, 4) router_split_kernel(
    const float* __restrict__ x, const float* __restrict__ br)
{
    __shared__ float  wsh[En * Dn];     // 24KB
    __shared__ double s_load[En];
    int warp = threadIdx.x >> 5;
    int lane = threadIdx.x & 31;
    if (threadIdx.x < En) s_load[threadIdx.x] = 0.0;
    for (int i = threadIdx.x * 4; i < En * Dn; i += 1024)
        *(float4*)(wsh + i) = *(const float4*)(g_WrT + i);
    __syncthreads();

    int t = blockIdx.x * 8 + warp;
    {
        const float* xr = x + (size_t)t * Dn;
        char* dh = (char*)g_Xh + (size_t)t * Dn * 2;

        float4 v[8];
#pragma unroll
        for (int jj = 0; jj < 8; jj++)
            v[jj] = *(const float4*)(xr + (lane + 32 * jj) * 4);

        float acc[En];
#pragma unroll
        for (int e = 0; e < En; e++) acc[e] = 0.0f;
#pragma unroll
        for (int jj = 0; jj < 8; jj++) {
            int d0 = (lane + 32 * jj) * 4;
#pragma unroll
            for (int e = 0; e < En; e++) {
                float4 w = *(const float4*)(wsh + e * Dn + d0);
                acc[e] = fmaf(v[jj].x, w.x, acc[e]);
                acc[e] = fmaf(v[jj].y, w.y, acc[e]);
                acc[e] = fmaf(v[jj].z, w.z, acc[e]);
                acc[e] = fmaf(v[jj].w, w.w, acc[e]);
            }
            *(uint2*)(dh + d0 * 2) = make_uint2(
                pkh(__float2half_rn(v[jj].x), __float2half_rn(v[jj].y)),
                pkh(__float2half_rn(v[jj].z), __float2half_rn(v[jj].w)));
        }
#pragma unroll
        for (int off = 16; off > 0; off >>= 1)
#pragma unroll
            for (int e = 0; e < En; e++)
                acc[e] += __shfl_xor_sync(0xffffffffu, acc[e], off);

        if (lane == 0) {
            float p[En];
            float m = -1e30f;
#pragma unroll
            for (int e = 0; e < En; e++) { p[e] = acc[e] + br[e]; m = fmaxf(m, p[e]); }
            float s = 0.0f;
#pragma unroll
            for (int e = 0; e < En; e++) { p[e] = expf(p[e] - m); s += p[e]; }
            float inv = 1.0f / s;
#pragma unroll
            for (int e = 0; e < En; e++)
                p[e] = 0.9f * p[e] * inv + (0.1f / 6.0f);
#pragma unroll
            for (int e = 0; e < En; e++)
                atomicAdd(&s_load[e], (double)p[e]);

            int i0 = 0;
#pragma unroll
            for (int e = 1; e < En; e++) if (p[e] > p[i0]) i0 = e;
            int i1 = (i0 == 0) ? 1 : 0;
#pragma unroll
            for (int e = 0; e < En; e++) if (e != i0 && p[e] > p[i1]) i1 = e;

            int pos0 = atomicAdd(&g_expert_count[i0], 1);
            g_expert_tok[i0 * Bn + pos0] = t;
            g_expert_wt[i0 * Bn + pos0] = p[i0];
            int pos1 = atomicAdd(&g_expert_count[i1], 1);
            g_expert_tok[i1 * Bn + pos1] = t | (1 << 30);
            g_expert_wt[i1 * Bn + pos1] = p[i1];
        }
    }
    __syncthreads();
    if (threadIdx.x < En)
        atomicAdd(&g_load_sums[threadIdx.x], s_load[threadIdx.x]);
}

// ---------------- kernel: aux scalar ----------------
__global__ void aux_kernel(float* __restrict__ out_aux) {
    double aux = 0.0;
#pragma unroll
    for (int e = 0; e < En; e++) {
        double load = g_load_sums[e] / (double)Bn;
        aux += load * log(load * (double)En + 1e-9);
    }
    out_aux[0] = (float)(aux / log((double)En + 1e-9));
}

// ---------------- kernel: expert MLP (pure fp16 MMA, fp32 accum) ----------------
// Arena (144KB + pad):
//  GEMM1 (3-stage): B(c) = sb + 49152*(c%3): Xh+0(16K) W+16384(32K)
//  H panels (post-GEMM1): 4 x 16K at sb+0..65535
//  GEMM2 (4-stage): C(it) = sb + 65536 + 16384*(it%4)
#define ARENA_BYTES (147456 + 1024)
extern __shared__ char dsm[];

__global__ void __launch_bounds__(512, 1) expert_kernel(
    const float* __restrict__ b1g, const float* __restrict__ b2g)
{
    __shared__ int   toks[TMk];
    __shared__ int   tslot[TMk];
    __shared__ float twt[TMk];
    __shared__ float b1s[Hn];
    __shared__ float b2s[Dn];

    int e = blockIdx.y;
    int cnt = g_expert_count[e];
    int base = blockIdx.x * TMk;
    if (base >= cnt) return;

    int tid = threadIdx.x;
    int wid = tid >> 5, lane = tid & 31;

    uint32_t raw = smem_u32(dsm);
    uint32_t sb  = (raw + 1023u) & ~1023u;
    char* arena  = dsm + (sb - raw);

    if (tid < TMk) {
        int i = base + tid;
        if (i < cnt) {
            int v = g_expert_tok[e * Bn + i];
            toks[tid] = v & 0x3FFFFFFF; tslot[tid] = v >> 30;
            twt[tid] = g_expert_wt[e * Bn + i];
        } else { toks[tid] = 0; tslot[tid] = 0; twt[tid] = 0.0f; }
    }
    if (tid < Hn) b1s[tid] = b1g[e * Hn + tid];
    for (int f = tid; f < Dn; f += 512) b2s[f] = b2g[e * Dn + f];
    __syncthreads();

    // ---- fragment address constants ----
    int g  = lane >> 3, r = lane & 7;
    int arow = (g & 1) * 8 + r, akoff = (g >> 1) * 16;
    int brow = (g >> 1) * 8 + r, bkoff = (g & 1) * 16;
    int warpM = wid & 3, warpN = wid >> 2;

    uint32_t aoff[2];
    aoff[0] = (uint32_t)(warpM * 32 + arow) * 128 + akoff;
    aoff[1] = aoff[0] + 16 * 128;
    uint32_t boff1[4];
#pragma unroll
    for (int j2 = 0; j2 < 4; j2++)
        boff1[j2] = (uint32_t)(warpN * 64 + j2 * 16 + brow) * 128 + bkoff;

    // ---- staging tables ----
    const char* srcX[2]; uint32_t dstX[2];
#pragma unroll
    for (int p = 0; p < 2; p++) {
        int f = tid + p * 512, row = f >> 3, seg = f & 7;
        srcX[p] = (const char*)(g_Xh + (size_t)toks[row] * Dn) + seg * 16;
        dstX[p] = sw((uint32_t)row * 128 + seg * 16);
    }
    const __half* W1t = g_W1T + (size_t)e * Hn * Dn;
    const char* srcW[4]; uint32_t dstW[4];
#pragma unroll
    for (int p = 0; p < 4; p++) {
        int f = tid + p * 512, row = f >> 3, seg = f & 7;
        srcW[p] = (const char*)(W1t + (size_t)row * Dn) + seg * 16;
        dstW[p] = sw((uint32_t)row * 128 + seg * 16);
    }

    auto stage1 = [&](int ci, uint32_t bb) {
        uint32_t o = (uint32_t)ci * 128;
#pragma unroll
        for (int p = 0; p < 2; p++)
            cpa(bb + dstX[p], srcX[p] + o);
#pragma unroll
        for (int p = 0; p < 4; p++)
            cpa(bb + 16384 + dstW[p], srcW[p] + o);
    };

    // ================= GEMM1: C1[128x256] = X[128x1024] @ W1 (3-stage) =========
    float acc[2][8][4];
#pragma unroll
    for (int i = 0; i < 2; i++)
#pragma unroll
        for (int j = 0; j < 8; j++)
#pragma unroll
            for (int q = 0; q < 4; q++) acc[i][j][q] = 0.0f;

    stage1(0, sb);         cp_commit();
    stage1(1, sb + 49152); cp_commit();

    for (int ci = 0; ci < 16; ci++) {
        if (ci == 15) cp_wait0(); else cp_wait1();
        __syncthreads();
        if (ci + 2 < 16) { stage1(ci + 2, sb + 49152u * ((ci + 2) % 3)); cp_commit(); }

        uint32_t cb = sb + 49152u * (ci % 3);
        uint32_t xh = cb, wh = cb + 16384;
#pragma unroll
        for (int ks = 0; ks < 4; ks++) {
            uint32_t Ah[2][4];
#pragma unroll
            for (int i = 0; i < 2; i++)
                ldsm4(Ah[i], xh + sw(aoff[i] + ks * 32));
#pragma unroll
            for (int j2 = 0; j2 < 4; j2++) {
                uint32_t Bh[4];
                ldsm4(Bh, wh + sw(boff1[j2] + ks * 32));
#pragma unroll
                for (int i = 0; i < 2; i++) {
                    mma_h(acc[i][2 * j2],     Ah[i], Bh[0], Bh[1]);
                    mma_h(acc[i][2 * j2 + 1], Ah[i], Bh[2], Bh[3]);
                }
            }
        }
    }
    __syncthreads();   // all GEMM1 reads done before H overwrites arena

    // ---- prefetch first three GEMM2 W2 stages ----
    const __half* W2t = g_W2T + (size_t)e * Dn * Hn;
    uint32_t srcO2[2], dst2[2];
#pragma unroll
    for (int p = 0; p < 2; p++) {
        int f = tid + p * 512, row = f >> 3, seg = f & 7;
        srcO2[p] = (uint32_t)row * 512 + seg * 16;
        dst2[p]  = sw((uint32_t)row * 128 + seg * 16);
    }
    auto stage2 = [&](int it, uint32_t bb) {
        int np = it >> 2, kc = it & 3;
        uint32_t o = (uint32_t)np * 65536 + (uint32_t)kc * 128;
#pragma unroll
        for (int p = 0; p < 2; p++)
            cpa(bb + dst2[p], (const char*)W2t + srcO2[p] + o);
    };
    stage2(0, sb + 65536);             cp_commit();
    stage2(1, sb + 65536 + 16384);     cp_commit();
    stage2(2, sb + 65536 + 32768);     cp_commit();

    // ---- epilogue 1: bias + GELU -> fp16 H panels ----
    {
        int mb = warpM * 32, nb = warpN * 64;
#pragma unroll
        for (int i = 0; i < 2; i++)
#pragma unroll
            for (int j = 0; j < 8; j++) {
                int m0 = mb + i * 16 + (lane >> 2);
                int n0 = nb + j * 8 + (lane & 3) * 2;
                float bb0 = b1s[n0], bb1 = b1s[n0 + 1];
#pragma unroll
                for (int hr = 0; hr < 2; hr++) {
                    int m = m0 + hr * 8;
                    float v0 = gelu(acc[i][j][hr * 2]     + bb0);
                    float v1 = gelu(acc[i][j][hr * 2 + 1] + bb1);
                    uint32_t off = ((uint32_t)(n0 >> 6)) * 16384 + sw((uint32_t)m * 128 + (n0 & 63) * 2);
                    *(uint32_t*)(arena + off) = pkh(__float2half_rn(v0), __float2half_rn(v1));
                }
            }
    }

    // ================= GEMM2: out[128x1024] = H[128x256] @ W2 (4-stage) =========
    uint32_t boff2[2];
#pragma unroll
    for (int j2 = 0; j2 < 2; j2++)
        boff2[j2] = (uint32_t)(warpN * 32 + j2 * 16 + brow) * 128 + bkoff;

    float acc2[2][4][4];

    for (int it = 0; it < 32; it++) {
        int np = it >> 2, kc = it & 3;
        if (it < 30) cp_wait2(); else if (it == 30) cp_wait1(); else cp_wait0();
        __syncthreads();
        if (it + 3 < 32) { stage2(it + 3, sb + 65536 + 16384u * ((it + 3) % 4)); cp_commit(); }

        if (kc == 0) {
#pragma unroll
            for (int i = 0; i < 2; i++)
#pragma unroll
                for (int j = 0; j < 4; j++)
#pragma unroll
                    for (int q = 0; q < 4; q++) acc2[i][j][q] = 0.0f;
        }

        uint32_t ah = sb + kc * 16384;
        uint32_t cb = sb + 65536 + 16384u * (it % 4);
#pragma unroll
        for (int ks = 0; ks < 4; ks++) {
            uint32_t Ah[2][4];
#pragma unroll
            for (int i = 0; i < 2; i++)
                ldsm4(Ah[i], ah + sw(aoff[i] + ks * 32));
#pragma unroll
            for (int j2 = 0; j2 < 2; j2++) {
                uint32_t Bh[4];
                ldsm4(Bh, cb + sw(boff2[j2] + ks * 32));
#pragma unroll
                for (int i = 0; i < 2; i++) {
                    mma_h(acc2[i][2 * j2],     Ah[i], Bh[0], Bh[1]);
                    mma_h(acc2[i][2 * j2 + 1], Ah[i], Bh[2], Bh[3]);
                }
            }
        }

        if (kc == 3) {
            int mb = warpM * 32, nb = warpN * 32;
#pragma unroll
            for (int i = 0; i < 2; i++)
#pragma unroll
                for (int j = 0; j < 4; j++) {
                    int m0 = mb + i * 16 + (lane >> 2);
                    int n0 = np * 128 + nb + j * 8 + (lane & 3) * 2;
                    float bb0 = b2s[n0], bb1 = b2s[n0 + 1];
#pragma unroll
                    for (int hr = 0; hr < 2; hr++) {
                        int m = m0 + hr * 8;
                        if (base + m < cnt) {
                            int   tok  = toks[m];
                            float wgt  = twt[m];
                            float o0 = wgt * (acc2[i][j][hr * 2]     + bb0);
                            float o1 = wgt * (acc2[i][j][hr * 2 + 1] + bb1);
                            uint32_t* dst = (uint32_t*)((char*)g_bufh +
                                ((size_t)tslot[m] * BD + (size_t)tok * Dn + n0) * 2);
                            *dst = pkh(__float2half_rn(o0), __float2half_rn(o1));
                        }
                    }
                }
        }
    }
}

// ---------------- kernel: combine the two fp16 slots -> fp32 out ----------------
__global__ void combine_kernel(float* __restrict__ out) {
    size_t i = ((size_t)blockIdx.x * 512 + threadIdx.x) * 4;
    uint2 pa = *(const uint2*)((const char*)g_bufh + i * 2);
    uint2 pb = *(const uint2*)((const char*)g_bufh + ((size_t)BD + i) * 2);
    __half2 a0 = *(__half2*)&pa.x, a1 = *(__half2*)&pa.y;
    __half2 b0 = *(__half2*)&pb.x, b1 = *(__half2*)&pb.y;
    float2 fa0 = __half22float2(a0), fa1 = __half22float2(a1);
    float2 fb0 = __half22float2(b0), fb1 = __half22float2(b1);
    *(float4*)(out + i) = make_float4(fa0.x + fb0.x, fa0.y + fb0.y,
                                      fa1.x + fb1.x, fa1.y + fb1.y);
}

// ---------------- launch ----------------
extern "C" void kernel_launch(void* const* d_in, const int* in_sizes, int n_in,
                              void* d_out, int out_size) {
    const float* x  = (const float*)d_in[0];
    const float* Wr = (const float*)d_in[1];
    const float* br = (const float*)d_in[2];
    const float* W1 = (const float*)d_in[3];
    const float* b1 = (const float*)d_in[4];
    const float* W2 = (const float*)d_in[5];
    const float* b2 = (const float*)d_in[6];
    float* out = (float*)d_out;

    // One-time host resources (created on first, non-captured call; reused under
    // capture — work per call is identical and deterministic).
    static cudaStream_t s_side = nullptr;
    static cudaEvent_t  ev_fork = nullptr, ev_join = nullptr;
    if (!s_side) {
        cudaStreamCreateWithFlags(&s_side, cudaStreamNonBlocking);
        cudaEventCreateWithFlags(&ev_fork, cudaEventDisableTiming);
        cudaEventCreateWithFlags(&ev_join, cudaEventDisableTiming);
    }

    cudaFuncSetAttribute(expert_kernel,
                         cudaFuncAttributeMaxDynamicSharedMemorySize, ARENA_BYTES);

    prep_small<<<(Dn * En + 255) / 256, 256>>>(Wr);

    // fork: weight transposes run concurrently with the router
    cudaEventRecord(ev_fork, 0);
    cudaStreamWaitEvent(s_side, ev_fork, 0);
    transpose_half_kernel<<<dim3(8, 32, En), dim3(32, 8), 0, s_side>>>(W1, Dn, Hn, 0);
    transpose_half_kernel<<<dim3(32, 8, En), dim3(32, 8), 0, s_side>>>(W2, Hn, Dn, 1);
    cudaEventRecord(ev_join, s_side);

    router_split_kernel<<<Bn / 8, 256>>>(x, br);
    if (out_size > BD)
        aux_kernel<<<1, 1>>>(out + (size_t)BD);

    cudaStreamWaitEvent(0, ev_join, 0);   // join before expert
    expert_kernel<<<dim3(Bn / TMk, En), 512, ARENA_BYTES>>>(b1, b2);
    combine_kernel<<<BD / 2048, 512>>>(out);
}